// round 7
// baseline (speedup 1.0000x reference)
#include <cuda_runtime.h>
#include <math.h>

// Problem shapes (fixed by the dataset)
#define BB    2
#define NC    512
#define NF    8192
#define MM    8192
#define NT    256
#define SLICE 2048      // targets per block slice
#define NSL   4         // slices (8192 / 2048)
#define QPT   4         // queries per thread (main roles)
#define EPSF  1e-12f

typedef unsigned long long ull;

// ---------------- scratch (__device__ globals; no allocation allowed) ----------------
__device__ float g_av [BB][NSL][NF];     // fine->target partial min value per slice
__device__ int   g_ai [BB][NSL][NF];     // fine->target partial argmin index per slice
__device__ float g_tv [BB][NSL][MM];     // target->fine partial min per slice
__device__ float g_tcv[BB][NSL][MM];     // target->coarse partial min per coarse sub-slice
__device__ float g_cv [BB][NSL][NC];     // coarse->target partial min per slice
__device__ float g_nt [BB * NF * 3];     // gathered nearest target per fine point
__device__ float g_pf [BB][32][4];       // fine combine blocks: sum d1, sum zf^2, sum znt^2, sum ydiff^2
__device__ float g_pt [BB][32][2];       // target combine blocks: sum d2f, sum d2c
__device__ float g_pc [BB][2];           // coarse combine blocks: sum d1c
__device__ float g_pv [BB][32][2];       // volume partials: fine, new_target

// ---------------- packed f32x2 helpers (per-half bit-identical to scalar) ----------------
__device__ __forceinline__ ull pack2(float lo, float hi) {
    ull r; asm("mov.b64 %0, {%1, %2};" : "=l"(r) : "f"(lo), "f"(hi)); return r;
}
__device__ __forceinline__ void unpack2(ull v, float& lo, float& hi) {
    asm("mov.b64 {%0, %1}, %2;" : "=f"(lo), "=f"(hi) : "l"(v));
}
__device__ __forceinline__ ull mul2(ull a, ull b) {
    ull r; asm("mul.rn.f32x2 %0, %1, %2;" : "=l"(r) : "l"(a), "l"(b)); return r;
}
__device__ __forceinline__ ull fma2(ull a, ull b, ull c) {
    ull r; asm("fma.rn.f32x2 %0, %1, %2, %3;" : "=l"(r) : "l"(a), "l"(b), "l"(c)); return r;
}

// Deterministic in-block tree reduction
__device__ __forceinline__ float blockSum(float v, float* sh) {
    int t = threadIdx.x;
    sh[t] = v;
    __syncthreads();
#pragma unroll
    for (int s = NT / 2; s > 0; s >>= 1) {
        if (t < s) sh[t] += sh[t + s];
        __syncthreads();
    }
    float r = sh[0];
    __syncthreads();
    return r;
}

// Load `count` points (count even) starting at src[t0] into pair-structs:
//   xy[p] = (x_{2p}, x_{2p+1}, y_{2p}, y_{2p+1}),  zw[p] = (z_{2p}, z_{2p+1}, w_{2p}, w_{2p+1})
__device__ __forceinline__ void loadPairs(float4* xy, float4* zw,
                                          const float* __restrict__ src,
                                          int t0, int count) {
    for (int p = threadIdx.x; p < count / 2; p += NT) {
        const int j0 = t0 + 2 * p;
        const float x0 = src[j0 * 3 + 0], y0 = src[j0 * 3 + 1], z0 = src[j0 * 3 + 2];
        const float x1 = src[j0 * 3 + 3], y1 = src[j0 * 3 + 4], z1 = src[j0 * 3 + 5];
        xy[p] = make_float4(x0, x1, y0, y1);
        zw[p] = make_float4(z0, z1,
                            x0 * x0 + y0 * y0 + z0 * z0,
                            x1 * x1 + y1 * y1 + z1 * z1);
    }
}

// Main pass: grid = (68, BB).
//  bx in [0,32):  fine->target argmin.  qblock = bx>>2, slice = bx&3
//  bx in [32,64): target->fine min + target->coarse min. same decomposition
//  bx in [64,68): coarse->target min. slice = bx-64, all 512 coarse queries (Q=2)
__global__ void __launch_bounds__(NT) nn_kernel(const float* __restrict__ sc,
                                                const float* __restrict__ sf,
                                                const float* __restrict__ tp)
{
    __shared__ float4 tXY[SLICE / 2], tZW[SLICE / 2];
    __shared__ float4 cXY[64], cZW[64];   // coarse sub-slice pairs (128 points)

    const int b   = blockIdx.y;
    const int bx  = blockIdx.x;
    const int tid = threadIdx.x;

    const float* tgt = tp + (size_t)b * MM * 3;
    const float* fin = sf + (size_t)b * NF * 3;
    const float* crs = sc + (size_t)b * NC * 3;

    if (bx < 32) {
        // ================= fine -> target : partial argmin over one slice =================
        const int qb    = bx >> 2;
        const int slice = bx & 3;
        const int base  = slice * SLICE;

        loadPairs(tXY, tZW, tgt, base, SLICE);

        ull qx2[QPT], qy2[QPT], qz2[QPT];
        float b0[QPT], b1[QPT];
        int   j0[QPT], j1[QPT];
#pragma unroll
        for (int q = 0; q < QPT; q++) {
            const int qi = qb * (NT * QPT) + q * NT + tid;
            const float qx = fin[qi * 3 + 0];
            const float qy = fin[qi * 3 + 1];
            const float qz = fin[qi * 3 + 2];
            qx2[q] = pack2(qx, qx); qy2[q] = pack2(qy, qy); qz2[q] = pack2(qz, qz);
            b0[q] = 3.0e38f; b1[q] = 3.0e38f; j0[q] = base; j1[q] = base + 1;
        }
        const ull NEG2 = pack2(-2.0f, -2.0f);
        __syncthreads();

#pragma unroll 2
        for (int p = 0; p < SLICE / 2; p++) {
            const float4 vxy = tXY[p];
            const float4 vzw = tZW[p];
            const ull X2 = pack2(vxy.x, vxy.y);
            const ull Y2 = pack2(vxy.z, vxy.w);
            const ull Z2 = pack2(vzw.x, vzw.y);
            const ull W2 = pack2(vzw.z, vzw.w);
            const int je = base + 2 * p;
#pragma unroll
            for (int q = 0; q < QPT; q++) {
                const ull xy2 = fma2(qz2[q], Z2, fma2(qy2[q], Y2, mul2(qx2[q], X2)));
                const ull t2  = fma2(NEG2, xy2, W2);
                float tlo, thi; unpack2(t2, tlo, thi);
                if (tlo < b0[q]) { b0[q] = tlo; j0[q] = je; }
                if (thi < b1[q]) { b1[q] = thi; j1[q] = je + 1; }
            }
        }
#pragma unroll
        for (int q = 0; q < QPT; q++) {
            const int qi = qb * (NT * QPT) + q * NT + tid;
            float best = b0[q]; int jb = j0[q];
            if (b1[q] < best) { best = b1[q]; jb = j1[q]; }
            g_av[b][slice][qi] = best;
            g_ai[b][slice][qi] = jb;
        }
    } else if (bx < 64) {
        // ============ target -> fine (min) and target -> coarse (min), one slice ============
        const int r     = bx - 32;
        const int qb    = r >> 2;
        const int slice = r & 3;
        const int base  = slice * SLICE;

        loadPairs(tXY, tZW, fin, base, SLICE);
        loadPairs(cXY, cZW, crs, slice * 128, 128);

        ull qx2[QPT], qy2[QPT], qz2[QPT];
        float mf[QPT * 2], mc[QPT * 2];
#pragma unroll
        for (int q = 0; q < QPT; q++) {
            const int qj = qb * (NT * QPT) + q * NT + tid;
            const float qx = tgt[qj * 3 + 0];
            const float qy = tgt[qj * 3 + 1];
            const float qz = tgt[qj * 3 + 2];
            qx2[q] = pack2(qx, qx); qy2[q] = pack2(qy, qy); qz2[q] = pack2(qz, qz);
            mf[2 * q] = 3.0e38f; mf[2 * q + 1] = 3.0e38f;
            mc[2 * q] = 3.0e38f; mc[2 * q + 1] = 3.0e38f;
        }
        const ull NEG2 = pack2(-2.0f, -2.0f);
        __syncthreads();

#pragma unroll 2
        for (int p = 0; p < SLICE / 2; p++) {
            const float4 vxy = tXY[p];
            const float4 vzw = tZW[p];
            const ull X2 = pack2(vxy.x, vxy.y);
            const ull Y2 = pack2(vxy.z, vxy.w);
            const ull Z2 = pack2(vzw.x, vzw.y);
            const ull W2 = pack2(vzw.z, vzw.w);
#pragma unroll
            for (int q = 0; q < QPT; q++) {
                const ull xy2 = fma2(qz2[q], Z2, fma2(qy2[q], Y2, mul2(qx2[q], X2)));
                const ull t2  = fma2(NEG2, xy2, W2);
                float tlo, thi; unpack2(t2, tlo, thi);
                mf[2 * q]     = fminf(mf[2 * q],     tlo);
                mf[2 * q + 1] = fminf(mf[2 * q + 1], thi);
            }
        }
#pragma unroll
        for (int p = 0; p < 64; p++) {
            const float4 vxy = cXY[p];
            const float4 vzw = cZW[p];
            const ull X2 = pack2(vxy.x, vxy.y);
            const ull Y2 = pack2(vxy.z, vxy.w);
            const ull Z2 = pack2(vzw.x, vzw.y);
            const ull W2 = pack2(vzw.z, vzw.w);
#pragma unroll
            for (int q = 0; q < QPT; q++) {
                const ull xy2 = fma2(qz2[q], Z2, fma2(qy2[q], Y2, mul2(qx2[q], X2)));
                const ull t2  = fma2(NEG2, xy2, W2);
                float tlo, thi; unpack2(t2, tlo, thi);
                mc[2 * q]     = fminf(mc[2 * q],     tlo);
                mc[2 * q + 1] = fminf(mc[2 * q + 1], thi);
            }
        }
#pragma unroll
        for (int q = 0; q < QPT; q++) {
            const int qj = qb * (NT * QPT) + q * NT + tid;
            g_tv [b][slice][qj] = fminf(mf[2 * q], mf[2 * q + 1]);
            g_tcv[b][slice][qj] = fminf(mc[2 * q], mc[2 * q + 1]);
        }
    } else {
        // ================= coarse -> target : partial min over one slice =================
        const int slice = bx - 64;
        const int base  = slice * SLICE;

        loadPairs(tXY, tZW, tgt, base, SLICE);

        ull qx2[2], qy2[2], qz2[2];
        float m[4];
#pragma unroll
        for (int q = 0; q < 2; q++) {
            const int ci = q * NT + tid;
            const float qx = crs[ci * 3 + 0];
            const float qy = crs[ci * 3 + 1];
            const float qz = crs[ci * 3 + 2];
            qx2[q] = pack2(qx, qx); qy2[q] = pack2(qy, qy); qz2[q] = pack2(qz, qz);
            m[2 * q] = 3.0e38f; m[2 * q + 1] = 3.0e38f;
        }
        const ull NEG2 = pack2(-2.0f, -2.0f);
        __syncthreads();

#pragma unroll 2
        for (int p = 0; p < SLICE / 2; p++) {
            const float4 vxy = tXY[p];
            const float4 vzw = tZW[p];
            const ull X2 = pack2(vxy.x, vxy.y);
            const ull Y2 = pack2(vxy.z, vxy.w);
            const ull Z2 = pack2(vzw.x, vzw.y);
            const ull W2 = pack2(vzw.z, vzw.w);
#pragma unroll
            for (int q = 0; q < 2; q++) {
                const ull xy2 = fma2(qz2[q], Z2, fma2(qy2[q], Y2, mul2(qx2[q], X2)));
                const ull t2  = fma2(NEG2, xy2, W2);
                float tlo, thi; unpack2(t2, tlo, thi);
                m[2 * q]     = fminf(m[2 * q],     tlo);
                m[2 * q + 1] = fminf(m[2 * q + 1], thi);
            }
        }
#pragma unroll
        for (int q = 0; q < 2; q++) {
            const int ci = q * NT + tid;
            g_cv[b][slice][ci] = fminf(m[2 * q], m[2 * q + 1]);
        }
    }
}

// Combine partial slices + per-query epilogue + block partial sums.
// grid = (66, BB): bx<32 fine, [32,64) target, [64,66) coarse
__global__ void __launch_bounds__(NT) combine_kernel(const float* __restrict__ sc,
                                                     const float* __restrict__ sf,
                                                     const float* __restrict__ tp)
{
    __shared__ float sred[NT];
    const int b   = blockIdx.y;
    const int bx  = blockIdx.x;
    const int tid = threadIdx.x;

    if (bx < 32) {
        const int qi = bx * NT + tid;
        // argmin across slices in ascending order (strict < keeps earliest)
        float best = g_av[b][0][qi]; int jb = g_ai[b][0][qi];
#pragma unroll
        for (int s = 1; s < NSL; s++) {
            const float v = g_av[b][s][qi];
            if (v < best) { best = v; jb = g_ai[b][s][qi]; }
        }
        const float* fin = sf + (size_t)b * NF * 3;
        const float* tgt = tp + (size_t)b * MM * 3;
        const float qx = fin[qi * 3 + 0];
        const float qy = fin[qi * 3 + 1];
        const float qz = fin[qi * 3 + 2];
        const float qq = qx * qx + qy * qy + qz * qz;

        const float d  = fmaxf(qq + best, 0.0f);
        const float d1 = sqrtf(fmaxf(d, EPSF));

        const float nx = tgt[jb * 3 + 0];
        const float ny = tgt[jb * 3 + 1];
        const float nz = tgt[jb * 3 + 2];
        const int o = (b * NF + qi) * 3;
        g_nt[o + 0] = nx; g_nt[o + 1] = ny; g_nt[o + 2] = nz;

        const float yd = qy - ny;
        const float r0 = blockSum(d1,      sred);
        const float r1 = blockSum(qz * qz, sred);
        const float r2 = blockSum(nz * nz, sred);
        const float r3 = blockSum(yd * yd, sred);
        if (tid == 0) {
            g_pf[b][bx][0] = r0; g_pf[b][bx][1] = r1;
            g_pf[b][bx][2] = r2; g_pf[b][bx][3] = r3;
        }
    } else if (bx < 64) {
        const int qj = (bx - 32) * NT + tid;
        float mF = g_tv[b][0][qj], mC = g_tcv[b][0][qj];
#pragma unroll
        for (int s = 1; s < NSL; s++) {
            mF = fminf(mF, g_tv[b][s][qj]);
            mC = fminf(mC, g_tcv[b][s][qj]);
        }
        const float* tgt = tp + (size_t)b * MM * 3;
        const float qx = tgt[qj * 3 + 0];
        const float qy = tgt[qj * 3 + 1];
        const float qz = tgt[qj * 3 + 2];
        const float qq = qx * qx + qy * qy + qz * qz;

        const float d2f = sqrtf(fmaxf(fmaxf(qq + mF, 0.0f), EPSF));
        const float d2c = sqrtf(fmaxf(fmaxf(qq + mC, 0.0f), EPSF));
        const float r0 = blockSum(d2f, sred);
        const float r1 = blockSum(d2c, sred);
        if (tid == 0) { g_pt[b][bx - 32][0] = r0; g_pt[b][bx - 32][1] = r1; }
    } else {
        const int ci = (bx - 64) * NT + tid;
        float m = g_cv[b][0][ci];
#pragma unroll
        for (int s = 1; s < NSL; s++) m = fminf(m, g_cv[b][s][ci]);

        const float* crs = sc + (size_t)b * NC * 3;
        const float qx = crs[ci * 3 + 0];
        const float qy = crs[ci * 3 + 1];
        const float qz = crs[ci * 3 + 2];
        const float qq = qx * qx + qy * qy + qz * qz;

        const float d1c = sqrtf(fmaxf(fmaxf(qq + m, 0.0f), EPSF));
        const float r0 = blockSum(d1c, sred);
        if (tid == 0) g_pc[b][bx - 64] = r0;
    }
}

// Wedge-product volume partials for source_fine and gathered new_target.
__global__ void __launch_bounds__(NT) volume_kernel(const float* __restrict__ sf)
{
    __shared__ float sred[NT];
    const int b   = blockIdx.y;
    const int bx  = blockIdx.x;
    const int tid = threadIdx.x;
    const int i   = bx * NT + tid;

    float vf = 0.0f, vn = 0.0f;
    if (i < NF - 2) {
        const float* p = sf + (size_t)b * NF * 3 + (size_t)i * 3;
        float a0 = p[0], a1 = p[1], a2 = p[2];
        float e0 = p[3], e1 = p[4], e2 = p[5];
        float c0 = p[6], c1 = p[7], c2 = p[8];
        float cx = a1 * e2 - a2 * e1;
        float cy = a2 * e0 - a0 * e2;
        float cz = a0 * e1 - a1 * e0;
        vf = cx * c0 + cy * c1 + cz * c2;

        const float* q = g_nt + ((size_t)b * NF + i) * 3;
        a0 = q[0]; a1 = q[1]; a2 = q[2];
        e0 = q[3]; e1 = q[4]; e2 = q[5];
        c0 = q[6]; c1 = q[7]; c2 = q[8];
        cx = a1 * e2 - a2 * e1;
        cy = a2 * e0 - a0 * e2;
        cz = a0 * e1 - a1 * e0;
        vn = cx * c0 + cy * c1 + cz * c2;
    }
    const float r0 = blockSum(vf, sred);
    const float r1 = blockSum(vn, sred);
    if (tid == 0) { g_pv[b][bx][0] = r0; g_pv[b][bx][1] = r1; }
}

// Single-thread deterministic combine of all partials into the scalar loss.
__global__ void finalize_kernel(float* __restrict__ out)
{
    float S1f = 0.0f, Syd = 0.0f, S2f = 0.0f, S2c = 0.0f, S1c = 0.0f;
    float szf[BB], sznt[BB], vfb[BB], vnb[BB];
#pragma unroll
    for (int b = 0; b < BB; b++) { szf[b] = sznt[b] = vfb[b] = vnb[b] = 0.0f; }

    for (int b = 0; b < BB; b++) {
        for (int k = 0; k < 32; k++) {
            S1f     += g_pf[b][k][0];
            szf[b]  += g_pf[b][k][1];
            sznt[b] += g_pf[b][k][2];
            Syd     += g_pf[b][k][3];
            S2f     += g_pt[b][k][0];
            S2c     += g_pt[b][k][1];
            vfb[b]  += g_pv[b][k][0];
            vnb[b]  += g_pv[b][k][1];
        }
        S1c += g_pc[b][0] + g_pc[b][1];
    }

    const float la_f = 0.5f * (S1f / (float)(BB * NF) + S2f / (float)(BB * MM));
    const float la_c = 0.5f * (S1c / (float)(BB * NC) + S2c / (float)(BB * MM));
    const float lref = Syd / (float)(BB * NF);

    float lrot = 0.0f, lgeo = 0.0f;
    for (int b = 0; b < BB; b++) {
        const float dr = sqrtf(szf[b]) - sqrtf(sznt[b]);
        lrot += dr * dr;
        const float dg = (vfb[b] - vnb[b]) * (1.0f / 6.0f);
        lgeo += dg * dg;
    }
    lrot *= (1.0f / (float)BB);
    lgeo *= (1.0f / (float)BB);

    out[0] = lrot + lref + la_c + la_f + lgeo;
}

extern "C" void kernel_launch(void* const* d_in, const int* in_sizes, int n_in,
                              void* d_out, int out_size)
{
    const float* sc = (const float*)d_in[0];  // source_coarse (B, 512, 3)
    const float* sf = (const float*)d_in[1];  // source_fine   (B, 8192, 3)
    const float* tp = (const float*)d_in[2];  // target_points (B, 8192, 3)
    float* out = (float*)d_out;

    dim3 g1(68, BB);
    nn_kernel<<<g1, NT>>>(sc, sf, tp);

    dim3 g2(66, BB);
    combine_kernel<<<g2, NT>>>(sc, sf, tp);

    dim3 g3(32, BB);
    volume_kernel<<<g3, NT>>>(sf);

    finalize_kernel<<<1, 1>>>(out);
}

// round 8
// speedup vs baseline: 1.0261x; 1.0261x over previous
#include <cuda_runtime.h>
#include <math.h>

// Problem shapes (fixed by the dataset)
#define BB    2
#define NC    512
#define NF    8192
#define MM    8192
#define NT    256
#define SLICE 2048      // targets per block slice
#define NSL   4         // slices (8192 / 2048)
#define QPT   4         // queries per thread (main roles)
#define EPSF  1e-12f

typedef unsigned long long ull;

// ---------------- scratch (__device__ globals; no allocation allowed) ----------------
__device__ float g_av [BB][NSL][NF];     // fine->target partial min value per slice
__device__ int   g_ai [BB][NSL][NF];     // fine->target partial argmin index per slice
__device__ float g_tv [BB][NSL][MM];     // target->fine partial min per slice
__device__ float g_tcv[BB][NSL][MM];     // target->coarse partial min per coarse sub-slice
__device__ float g_cv [BB][NSL][NC];     // coarse->target partial min per slice
__device__ float g_nt [BB * NF * 3];     // gathered nearest target per fine point
__device__ float g_pf [BB][32][4];       // fine combine blocks: sum d1, sum zf^2, sum znt^2, sum ydiff^2
__device__ float g_pt [BB][32][2];       // target combine blocks: sum d2f, sum d2c
__device__ float g_pc [BB][2];           // coarse combine blocks: sum d1c

// ---------------- packed f32x2 helpers (per-half bit-identical to scalar) ----------------
__device__ __forceinline__ ull pack2(float lo, float hi) {
    ull r; asm("mov.b64 %0, {%1, %2};" : "=l"(r) : "f"(lo), "f"(hi)); return r;
}
__device__ __forceinline__ void unpack2(ull v, float& lo, float& hi) {
    asm("mov.b64 {%0, %1}, %2;" : "=f"(lo), "=f"(hi) : "l"(v));
}
__device__ __forceinline__ ull mul2(ull a, ull b) {
    ull r; asm("mul.rn.f32x2 %0, %1, %2;" : "=l"(r) : "l"(a), "l"(b)); return r;
}
__device__ __forceinline__ ull fma2(ull a, ull b, ull c) {
    ull r; asm("fma.rn.f32x2 %0, %1, %2, %3;" : "=l"(r) : "l"(a), "l"(b), "l"(c)); return r;
}

// Deterministic in-block tree reduction
__device__ __forceinline__ float blockSum(float v, float* sh) {
    int t = threadIdx.x;
    sh[t] = v;
    __syncthreads();
#pragma unroll
    for (int s = NT / 2; s > 0; s >>= 1) {
        if (t < s) sh[t] += sh[t + s];
        __syncthreads();
    }
    float r = sh[0];
    __syncthreads();
    return r;
}

// Load `count` points (count even) starting at src[t0] into pair-structs:
//   xy[p] = (x_{2p}, x_{2p+1}, y_{2p}, y_{2p+1}),  zw[p] = (z_{2p}, z_{2p+1}, w_{2p}, w_{2p+1})
__device__ __forceinline__ void loadPairs(float4* xy, float4* zw,
                                          const float* __restrict__ src,
                                          int t0, int count) {
    for (int p = threadIdx.x; p < count / 2; p += NT) {
        const int j0 = t0 + 2 * p;
        const float x0 = src[j0 * 3 + 0], y0 = src[j0 * 3 + 1], z0 = src[j0 * 3 + 2];
        const float x1 = src[j0 * 3 + 3], y1 = src[j0 * 3 + 4], z1 = src[j0 * 3 + 5];
        xy[p] = make_float4(x0, x1, y0, y1);
        zw[p] = make_float4(z0, z1,
                            x0 * x0 + y0 * y0 + z0 * z0,
                            x1 * x1 + y1 * y1 + z1 * z1);
    }
}

// Main pass: grid = (68, BB).
//  bx in [0,32):  fine->target argmin.  qblock = bx>>2, slice = bx&3
//  bx in [32,64): target->fine min + target->coarse min. same decomposition
//  bx in [64,68): coarse->target min. slice = bx-64, all 512 coarse queries (Q=2)
__global__ void __launch_bounds__(NT) nn_kernel(const float* __restrict__ sc,
                                                const float* __restrict__ sf,
                                                const float* __restrict__ tp)
{
    __shared__ float4 tXY[SLICE / 2], tZW[SLICE / 2];
    __shared__ float4 cXY[64], cZW[64];   // coarse sub-slice pairs (128 points)

    const int b   = blockIdx.y;
    const int bx  = blockIdx.x;
    const int tid = threadIdx.x;

    const float* tgt = tp + (size_t)b * MM * 3;
    const float* fin = sf + (size_t)b * NF * 3;
    const float* crs = sc + (size_t)b * NC * 3;

    if (bx < 32) {
        // ================= fine -> target : partial argmin over one slice =================
        // Pair-min trick: track min over pair-mins + best PAIR index only; recover the
        // element (lo/hi) in the epilogue by recomputing the two distances of the best
        // pair with identical arithmetic. First-occurrence semantics preserved:
        // strict < across ascending pairs; lo preferred on intra-pair tie.
        const int qb    = bx >> 2;
        const int slice = bx & 3;
        const int base  = slice * SLICE;

        loadPairs(tXY, tZW, tgt, base, SLICE);

        ull qx2[QPT], qy2[QPT], qz2[QPT];
        float best[QPT];
        int   pb[QPT];
#pragma unroll
        for (int q = 0; q < QPT; q++) {
            const int qi = qb * (NT * QPT) + q * NT + tid;
            const float qx = fin[qi * 3 + 0];
            const float qy = fin[qi * 3 + 1];
            const float qz = fin[qi * 3 + 2];
            qx2[q] = pack2(qx, qx); qy2[q] = pack2(qy, qy); qz2[q] = pack2(qz, qz);
            best[q] = 3.0e38f; pb[q] = 0;
        }
        const ull NEG2 = pack2(-2.0f, -2.0f);
        __syncthreads();

#pragma unroll 2
        for (int p = 0; p < SLICE / 2; p++) {
            const float4 vxy = tXY[p];
            const float4 vzw = tZW[p];
            const ull X2 = pack2(vxy.x, vxy.y);
            const ull Y2 = pack2(vxy.z, vxy.w);
            const ull Z2 = pack2(vzw.x, vzw.y);
            const ull W2 = pack2(vzw.z, vzw.w);
#pragma unroll
            for (int q = 0; q < QPT; q++) {
                const ull xy2 = fma2(qz2[q], Z2, fma2(qy2[q], Y2, mul2(qx2[q], X2)));
                const ull t2  = fma2(NEG2, xy2, W2);
                float tlo, thi; unpack2(t2, tlo, thi);
                const float m = fminf(tlo, thi);
                if (m < best[q]) { best[q] = m; pb[q] = p; }
            }
        }
#pragma unroll
        for (int q = 0; q < QPT; q++) {
            const int qi = qb * (NT * QPT) + q * NT + tid;
            // recover element within best pair (SMEM tile still resident)
            const int p = pb[q];
            const float4 vxy = tXY[p];
            const float4 vzw = tZW[p];
            const ull X2 = pack2(vxy.x, vxy.y);
            const ull Y2 = pack2(vxy.z, vxy.w);
            const ull Z2 = pack2(vzw.x, vzw.y);
            const ull W2 = pack2(vzw.z, vzw.w);
            const ull xy2 = fma2(qz2[q], Z2, fma2(qy2[q], Y2, mul2(qx2[q], X2)));
            const ull t2  = fma2(NEG2, xy2, W2);
            float tlo, thi; unpack2(t2, tlo, thi);
            const int jb = base + 2 * p + ((thi < tlo) ? 1 : 0);
            g_av[b][slice][qi] = best[q];
            g_ai[b][slice][qi] = jb;
        }
    } else if (bx < 64) {
        // ============ target -> fine (min) and target -> coarse (min), one slice ============
        const int r     = bx - 32;
        const int qb    = r >> 2;
        const int slice = r & 3;
        const int base  = slice * SLICE;

        loadPairs(tXY, tZW, fin, base, SLICE);
        loadPairs(cXY, cZW, crs, slice * 128, 128);

        ull qx2[QPT], qy2[QPT], qz2[QPT];
        float mf[QPT * 2], mc[QPT * 2];
#pragma unroll
        for (int q = 0; q < QPT; q++) {
            const int qj = qb * (NT * QPT) + q * NT + tid;
            const float qx = tgt[qj * 3 + 0];
            const float qy = tgt[qj * 3 + 1];
            const float qz = tgt[qj * 3 + 2];
            qx2[q] = pack2(qx, qx); qy2[q] = pack2(qy, qy); qz2[q] = pack2(qz, qz);
            mf[2 * q] = 3.0e38f; mf[2 * q + 1] = 3.0e38f;
            mc[2 * q] = 3.0e38f; mc[2 * q + 1] = 3.0e38f;
        }
        const ull NEG2 = pack2(-2.0f, -2.0f);
        __syncthreads();

#pragma unroll 2
        for (int p = 0; p < SLICE / 2; p++) {
            const float4 vxy = tXY[p];
            const float4 vzw = tZW[p];
            const ull X2 = pack2(vxy.x, vxy.y);
            const ull Y2 = pack2(vxy.z, vxy.w);
            const ull Z2 = pack2(vzw.x, vzw.y);
            const ull W2 = pack2(vzw.z, vzw.w);
#pragma unroll
            for (int q = 0; q < QPT; q++) {
                const ull xy2 = fma2(qz2[q], Z2, fma2(qy2[q], Y2, mul2(qx2[q], X2)));
                const ull t2  = fma2(NEG2, xy2, W2);
                float tlo, thi; unpack2(t2, tlo, thi);
                mf[2 * q]     = fminf(mf[2 * q],     tlo);
                mf[2 * q + 1] = fminf(mf[2 * q + 1], thi);
            }
        }
#pragma unroll
        for (int p = 0; p < 64; p++) {
            const float4 vxy = cXY[p];
            const float4 vzw = cZW[p];
            const ull X2 = pack2(vxy.x, vxy.y);
            const ull Y2 = pack2(vxy.z, vxy.w);
            const ull Z2 = pack2(vzw.x, vzw.y);
            const ull W2 = pack2(vzw.z, vzw.w);
#pragma unroll
            for (int q = 0; q < QPT; q++) {
                const ull xy2 = fma2(qz2[q], Z2, fma2(qy2[q], Y2, mul2(qx2[q], X2)));
                const ull t2  = fma2(NEG2, xy2, W2);
                float tlo, thi; unpack2(t2, tlo, thi);
                mc[2 * q]     = fminf(mc[2 * q],     tlo);
                mc[2 * q + 1] = fminf(mc[2 * q + 1], thi);
            }
        }
#pragma unroll
        for (int q = 0; q < QPT; q++) {
            const int qj = qb * (NT * QPT) + q * NT + tid;
            g_tv [b][slice][qj] = fminf(mf[2 * q], mf[2 * q + 1]);
            g_tcv[b][slice][qj] = fminf(mc[2 * q], mc[2 * q + 1]);
        }
    } else {
        // ================= coarse -> target : partial min over one slice =================
        const int slice = bx - 64;
        const int base  = slice * SLICE;

        loadPairs(tXY, tZW, tgt, base, SLICE);

        ull qx2[2], qy2[2], qz2[2];
        float m[4];
#pragma unroll
        for (int q = 0; q < 2; q++) {
            const int ci = q * NT + tid;
            const float qx = crs[ci * 3 + 0];
            const float qy = crs[ci * 3 + 1];
            const float qz = crs[ci * 3 + 2];
            qx2[q] = pack2(qx, qx); qy2[q] = pack2(qy, qy); qz2[q] = pack2(qz, qz);
            m[2 * q] = 3.0e38f; m[2 * q + 1] = 3.0e38f;
        }
        const ull NEG2 = pack2(-2.0f, -2.0f);
        __syncthreads();

#pragma unroll 2
        for (int p = 0; p < SLICE / 2; p++) {
            const float4 vxy = tXY[p];
            const float4 vzw = tZW[p];
            const ull X2 = pack2(vxy.x, vxy.y);
            const ull Y2 = pack2(vxy.z, vxy.w);
            const ull Z2 = pack2(vzw.x, vzw.y);
            const ull W2 = pack2(vzw.z, vzw.w);
#pragma unroll
            for (int q = 0; q < 2; q++) {
                const ull xy2 = fma2(qz2[q], Z2, fma2(qy2[q], Y2, mul2(qx2[q], X2)));
                const ull t2  = fma2(NEG2, xy2, W2);
                float tlo, thi; unpack2(t2, tlo, thi);
                m[2 * q]     = fminf(m[2 * q],     tlo);
                m[2 * q + 1] = fminf(m[2 * q + 1], thi);
            }
        }
#pragma unroll
        for (int q = 0; q < 2; q++) {
            const int ci = q * NT + tid;
            g_cv[b][slice][ci] = fminf(m[2 * q], m[2 * q + 1]);
        }
    }
}

// Combine partial slices + per-query epilogue + block partial sums.
// grid = (66, BB): bx<32 fine, [32,64) target, [64,66) coarse
__global__ void __launch_bounds__(NT) combine_kernel(const float* __restrict__ sc,
                                                     const float* __restrict__ sf,
                                                     const float* __restrict__ tp)
{
    __shared__ float sred[NT];
    const int b   = blockIdx.y;
    const int bx  = blockIdx.x;
    const int tid = threadIdx.x;

    if (bx < 32) {
        const int qi = bx * NT + tid;
        // argmin across slices in ascending order (strict < keeps earliest)
        float best = g_av[b][0][qi]; int jb = g_ai[b][0][qi];
#pragma unroll
        for (int s = 1; s < NSL; s++) {
            const float v = g_av[b][s][qi];
            if (v < best) { best = v; jb = g_ai[b][s][qi]; }
        }
        const float* fin = sf + (size_t)b * NF * 3;
        const float* tgt = tp + (size_t)b * MM * 3;
        const float qx = fin[qi * 3 + 0];
        const float qy = fin[qi * 3 + 1];
        const float qz = fin[qi * 3 + 2];
        const float qq = qx * qx + qy * qy + qz * qz;

        const float d  = fmaxf(qq + best, 0.0f);
        const float d1 = sqrtf(fmaxf(d, EPSF));

        const float nx = tgt[jb * 3 + 0];
        const float ny = tgt[jb * 3 + 1];
        const float nz = tgt[jb * 3 + 2];
        const int o = (b * NF + qi) * 3;
        g_nt[o + 0] = nx; g_nt[o + 1] = ny; g_nt[o + 2] = nz;

        const float yd = qy - ny;
        const float r0 = blockSum(d1,      sred);
        const float r1 = blockSum(qz * qz, sred);
        const float r2 = blockSum(nz * nz, sred);
        const float r3 = blockSum(yd * yd, sred);
        if (tid == 0) {
            g_pf[b][bx][0] = r0; g_pf[b][bx][1] = r1;
            g_pf[b][bx][2] = r2; g_pf[b][bx][3] = r3;
        }
    } else if (bx < 64) {
        const int qj = (bx - 32) * NT + tid;
        float mF = g_tv[b][0][qj], mC = g_tcv[b][0][qj];
#pragma unroll
        for (int s = 1; s < NSL; s++) {
            mF = fminf(mF, g_tv[b][s][qj]);
            mC = fminf(mC, g_tcv[b][s][qj]);
        }
        const float* tgt = tp + (size_t)b * MM * 3;
        const float qx = tgt[qj * 3 + 0];
        const float qy = tgt[qj * 3 + 1];
        const float qz = tgt[qj * 3 + 2];
        const float qq = qx * qx + qy * qy + qz * qz;

        const float d2f = sqrtf(fmaxf(fmaxf(qq + mF, 0.0f), EPSF));
        const float d2c = sqrtf(fmaxf(fmaxf(qq + mC, 0.0f), EPSF));
        const float r0 = blockSum(d2f, sred);
        const float r1 = blockSum(d2c, sred);
        if (tid == 0) { g_pt[b][bx - 32][0] = r0; g_pt[b][bx - 32][1] = r1; }
    } else {
        const int ci = (bx - 64) * NT + tid;
        float m = g_cv[b][0][ci];
#pragma unroll
        for (int s = 1; s < NSL; s++) m = fminf(m, g_cv[b][s][ci]);

        const float* crs = sc + (size_t)b * NC * 3;
        const float qx = crs[ci * 3 + 0];
        const float qy = crs[ci * 3 + 1];
        const float qz = crs[ci * 3 + 2];
        const float qq = qx * qx + qy * qy + qz * qz;

        const float d1c = sqrtf(fmaxf(fmaxf(qq + m, 0.0f), EPSF));
        const float r0 = blockSum(d1c, sred);
        if (tid == 0) g_pc[b][bx - 64] = r0;
    }
}

// Fused volume + finalize: ONE block, 256 threads.
// Threads stride the 8190 triples per batch (fixed order -> deterministic),
// tree-reduce, then thread 0 combines all partials into the scalar loss.
__global__ void __launch_bounds__(NT) tail_kernel(const float* __restrict__ sf,
                                                  float* __restrict__ out)
{
    __shared__ float sred[NT];
    __shared__ float svol[BB][2];
    const int tid = threadIdx.x;

    for (int b = 0; b < BB; b++) {
        float vf = 0.0f, vn = 0.0f;
        for (int i = tid; i < NF - 2; i += NT) {
            const float* p = sf + (size_t)b * NF * 3 + (size_t)i * 3;
            float a0 = p[0], a1 = p[1], a2 = p[2];
            float e0 = p[3], e1 = p[4], e2 = p[5];
            float c0 = p[6], c1 = p[7], c2 = p[8];
            float cx = a1 * e2 - a2 * e1;
            float cy = a2 * e0 - a0 * e2;
            float cz = a0 * e1 - a1 * e0;
            vf += cx * c0 + cy * c1 + cz * c2;

            const float* q = g_nt + ((size_t)b * NF + i) * 3;
            a0 = q[0]; a1 = q[1]; a2 = q[2];
            e0 = q[3]; e1 = q[4]; e2 = q[5];
            c0 = q[6]; c1 = q[7]; c2 = q[8];
            cx = a1 * e2 - a2 * e1;
            cy = a2 * e0 - a0 * e2;
            cz = a0 * e1 - a1 * e0;
            vn += cx * c0 + cy * c1 + cz * c2;
        }
        const float r0 = blockSum(vf, sred);
        const float r1 = blockSum(vn, sred);
        if (tid == 0) { svol[b][0] = r0; svol[b][1] = r1; }
    }
    __syncthreads();

    if (tid == 0) {
        float S1f = 0.0f, Syd = 0.0f, S2f = 0.0f, S2c = 0.0f, S1c = 0.0f;
        float szf[BB], sznt[BB];
#pragma unroll
        for (int b = 0; b < BB; b++) { szf[b] = sznt[b] = 0.0f; }

        for (int b = 0; b < BB; b++) {
            for (int k = 0; k < 32; k++) {
                S1f     += g_pf[b][k][0];
                szf[b]  += g_pf[b][k][1];
                sznt[b] += g_pf[b][k][2];
                Syd     += g_pf[b][k][3];
                S2f     += g_pt[b][k][0];
                S2c     += g_pt[b][k][1];
            }
            S1c += g_pc[b][0] + g_pc[b][1];
        }

        const float la_f = 0.5f * (S1f / (float)(BB * NF) + S2f / (float)(BB * MM));
        const float la_c = 0.5f * (S1c / (float)(BB * NC) + S2c / (float)(BB * MM));
        const float lref = Syd / (float)(BB * NF);

        float lrot = 0.0f, lgeo = 0.0f;
        for (int b = 0; b < BB; b++) {
            const float dr = sqrtf(szf[b]) - sqrtf(sznt[b]);
            lrot += dr * dr;
            const float dg = (svol[b][0] - svol[b][1]) * (1.0f / 6.0f);
            lgeo += dg * dg;
        }
        lrot *= (1.0f / (float)BB);
        lgeo *= (1.0f / (float)BB);

        out[0] = lrot + lref + la_c + la_f + lgeo;
    }
}

extern "C" void kernel_launch(void* const* d_in, const int* in_sizes, int n_in,
                              void* d_out, int out_size)
{
    const float* sc = (const float*)d_in[0];  // source_coarse (B, 512, 3)
    const float* sf = (const float*)d_in[1];  // source_fine   (B, 8192, 3)
    const float* tp = (const float*)d_in[2];  // target_points (B, 8192, 3)
    float* out = (float*)d_out;

    dim3 g1(68, BB);
    nn_kernel<<<g1, NT>>>(sc, sf, tp);

    dim3 g2(66, BB);
    combine_kernel<<<g2, NT>>>(sc, sf, tp);

    tail_kernel<<<1, NT>>>(sf, out);
}

// round 9
// speedup vs baseline: 1.3133x; 1.2799x over previous
#include <cuda_runtime.h>
#include <math.h>

// Problem shapes (fixed by the dataset)
#define BB    2
#define NC    512
#define NF    8192
#define MM    8192
#define NT    256
#define SLICE 1024      // targets per block slice
#define NSL   8         // slices (8192 / 1024)
#define QPT   4         // queries per thread (main roles)
#define EPSF  1e-12f

typedef unsigned long long ull;

// ---------------- scratch (__device__ globals; no allocation allowed) ----------------
__device__ float g_av [BB][NSL][NF];     // fine->target partial min value per slice
__device__ int   g_ai [BB][NSL][NF];     // fine->target partial argmin index per slice
__device__ float g_tv [BB][NSL][MM];     // target->fine partial min per slice
__device__ float g_tcv[BB][NSL][MM];     // target->coarse partial min per coarse sub-slice
__device__ float g_cv [BB][NSL][NC];     // coarse->target partial min per slice
__device__ float g_nt [BB * NF * 3];     // gathered nearest target per fine point
__device__ float g_pf [BB][32][4];       // fine combine: sum d1, sum zf^2, sum znt^2, sum ydiff^2
__device__ float g_pt [BB][32][2];       // target combine: sum d2f, sum d2c
__device__ float g_pc [BB][2];           // coarse combine: sum d1c
__device__ float g_pv [BB][32][2];       // volume partials (interior triples): fine, new_target

// ---------------- packed f32x2 helpers (per-half bit-identical to scalar) ----------------
__device__ __forceinline__ ull pack2(float lo, float hi) {
    ull r; asm("mov.b64 %0, {%1, %2};" : "=l"(r) : "f"(lo), "f"(hi)); return r;
}
__device__ __forceinline__ void unpack2(ull v, float& lo, float& hi) {
    asm("mov.b64 {%0, %1}, %2;" : "=f"(lo), "=f"(hi) : "l"(v));
}
__device__ __forceinline__ ull mul2(ull a, ull b) {
    ull r; asm("mul.rn.f32x2 %0, %1, %2;" : "=l"(r) : "l"(a), "l"(b)); return r;
}
__device__ __forceinline__ ull fma2(ull a, ull b, ull c) {
    ull r; asm("fma.rn.f32x2 %0, %1, %2, %3;" : "=l"(r) : "l"(a), "l"(b), "l"(c)); return r;
}

// Deterministic in-block tree reduction
__device__ __forceinline__ float blockSum(float v, float* sh) {
    int t = threadIdx.x;
    sh[t] = v;
    __syncthreads();
#pragma unroll
    for (int s = NT / 2; s > 0; s >>= 1) {
        if (t < s) sh[t] += sh[t + s];
        __syncthreads();
    }
    float r = sh[0];
    __syncthreads();
    return r;
}

// Load `count` points (count even) starting at src[t0] into pair-structs:
//   xy[p] = (x_{2p}, x_{2p+1}, y_{2p}, y_{2p+1}),  zw[p] = (z_{2p}, z_{2p+1}, w_{2p}, w_{2p+1})
__device__ __forceinline__ void loadPairs(float4* xy, float4* zw,
                                          const float* __restrict__ src,
                                          int t0, int count) {
    for (int p = threadIdx.x; p < count / 2; p += NT) {
        const int j0 = t0 + 2 * p;
        const float x0 = src[j0 * 3 + 0], y0 = src[j0 * 3 + 1], z0 = src[j0 * 3 + 2];
        const float x1 = src[j0 * 3 + 3], y1 = src[j0 * 3 + 4], z1 = src[j0 * 3 + 5];
        xy[p] = make_float4(x0, x1, y0, y1);
        zw[p] = make_float4(z0, z1,
                            x0 * x0 + y0 * y0 + z0 * z0,
                            x1 * x1 + y1 * y1 + z1 * z1);
    }
}

// Main pass: grid = (136, BB).
//  bx in [0,64):    fine->target argmin.  qblock = bx>>3, slice = bx&7
//  bx in [64,128):  target->fine min + target->coarse min. same decomposition
//  bx in [128,136): coarse->target min. slice = bx-128, all 512 coarse queries (QPT=2)
__global__ void __launch_bounds__(NT) nn_kernel(const float* __restrict__ sc,
                                                const float* __restrict__ sf,
                                                const float* __restrict__ tp)
{
    __shared__ float4 tXY[SLICE / 2], tZW[SLICE / 2];
    __shared__ float4 cXY[32], cZW[32];   // coarse sub-slice pairs (64 points)

    const int b   = blockIdx.y;
    const int bx  = blockIdx.x;
    const int tid = threadIdx.x;

    const float* tgt = tp + (size_t)b * MM * 3;
    const float* fin = sf + (size_t)b * NF * 3;
    const float* crs = sc + (size_t)b * NC * 3;

    if (bx < 64) {
        // ================= fine -> target : partial argmin over one slice =================
        // Pair-min trick: track min over pair-mins + best PAIR index; recover the element
        // in the epilogue by recomputing both halves with identical arithmetic.
        const int qb    = bx >> 3;
        const int slice = bx & 7;
        const int base  = slice * SLICE;

        loadPairs(tXY, tZW, tgt, base, SLICE);

        ull qx2[QPT], qy2[QPT], qz2[QPT];
        float best[QPT];
        int   pb[QPT];
#pragma unroll
        for (int q = 0; q < QPT; q++) {
            const int qi = qb * (NT * QPT) + q * NT + tid;
            const float qx = fin[qi * 3 + 0];
            const float qy = fin[qi * 3 + 1];
            const float qz = fin[qi * 3 + 2];
            qx2[q] = pack2(qx, qx); qy2[q] = pack2(qy, qy); qz2[q] = pack2(qz, qz);
            best[q] = 3.0e38f; pb[q] = 0;
        }
        const ull NEG2 = pack2(-2.0f, -2.0f);
        __syncthreads();

#pragma unroll 2
        for (int p = 0; p < SLICE / 2; p++) {
            const float4 vxy = tXY[p];
            const float4 vzw = tZW[p];
            const ull X2 = pack2(vxy.x, vxy.y);
            const ull Y2 = pack2(vxy.z, vxy.w);
            const ull Z2 = pack2(vzw.x, vzw.y);
            const ull W2 = pack2(vzw.z, vzw.w);
#pragma unroll
            for (int q = 0; q < QPT; q++) {
                const ull xy2 = fma2(qz2[q], Z2, fma2(qy2[q], Y2, mul2(qx2[q], X2)));
                const ull t2  = fma2(NEG2, xy2, W2);
                float tlo, thi; unpack2(t2, tlo, thi);
                const float m = fminf(tlo, thi);
                if (m < best[q]) { best[q] = m; pb[q] = p; }
            }
        }
#pragma unroll
        for (int q = 0; q < QPT; q++) {
            const int qi = qb * (NT * QPT) + q * NT + tid;
            const int p = pb[q];
            const float4 vxy = tXY[p];
            const float4 vzw = tZW[p];
            const ull X2 = pack2(vxy.x, vxy.y);
            const ull Y2 = pack2(vxy.z, vxy.w);
            const ull Z2 = pack2(vzw.x, vzw.y);
            const ull W2 = pack2(vzw.z, vzw.w);
            const ull xy2 = fma2(qz2[q], Z2, fma2(qy2[q], Y2, mul2(qx2[q], X2)));
            const ull t2  = fma2(NEG2, xy2, W2);
            float tlo, thi; unpack2(t2, tlo, thi);
            const int jb = base + 2 * p + ((thi < tlo) ? 1 : 0);
            g_av[b][slice][qi] = best[q];
            g_ai[b][slice][qi] = jb;
        }
    } else if (bx < 128) {
        // ============ target -> fine (min) and target -> coarse (min), one slice ============
        const int r     = bx - 64;
        const int qb    = r >> 3;
        const int slice = r & 7;
        const int base  = slice * SLICE;

        loadPairs(tXY, tZW, fin, base, SLICE);
        loadPairs(cXY, cZW, crs, slice * 64, 64);

        ull qx2[QPT], qy2[QPT], qz2[QPT];
        float mf[QPT * 2], mc[QPT * 2];
#pragma unroll
        for (int q = 0; q < QPT; q++) {
            const int qj = qb * (NT * QPT) + q * NT + tid;
            const float qx = tgt[qj * 3 + 0];
            const float qy = tgt[qj * 3 + 1];
            const float qz = tgt[qj * 3 + 2];
            qx2[q] = pack2(qx, qx); qy2[q] = pack2(qy, qy); qz2[q] = pack2(qz, qz);
            mf[2 * q] = 3.0e38f; mf[2 * q + 1] = 3.0e38f;
            mc[2 * q] = 3.0e38f; mc[2 * q + 1] = 3.0e38f;
        }
        const ull NEG2 = pack2(-2.0f, -2.0f);
        __syncthreads();

#pragma unroll 2
        for (int p = 0; p < SLICE / 2; p++) {
            const float4 vxy = tXY[p];
            const float4 vzw = tZW[p];
            const ull X2 = pack2(vxy.x, vxy.y);
            const ull Y2 = pack2(vxy.z, vxy.w);
            const ull Z2 = pack2(vzw.x, vzw.y);
            const ull W2 = pack2(vzw.z, vzw.w);
#pragma unroll
            for (int q = 0; q < QPT; q++) {
                const ull xy2 = fma2(qz2[q], Z2, fma2(qy2[q], Y2, mul2(qx2[q], X2)));
                const ull t2  = fma2(NEG2, xy2, W2);
                float tlo, thi; unpack2(t2, tlo, thi);
                mf[2 * q]     = fminf(mf[2 * q],     tlo);
                mf[2 * q + 1] = fminf(mf[2 * q + 1], thi);
            }
        }
#pragma unroll
        for (int p = 0; p < 32; p++) {
            const float4 vxy = cXY[p];
            const float4 vzw = cZW[p];
            const ull X2 = pack2(vxy.x, vxy.y);
            const ull Y2 = pack2(vxy.z, vxy.w);
            const ull Z2 = pack2(vzw.x, vzw.y);
            const ull W2 = pack2(vzw.z, vzw.w);
#pragma unroll
            for (int q = 0; q < QPT; q++) {
                const ull xy2 = fma2(qz2[q], Z2, fma2(qy2[q], Y2, mul2(qx2[q], X2)));
                const ull t2  = fma2(NEG2, xy2, W2);
                float tlo, thi; unpack2(t2, tlo, thi);
                mc[2 * q]     = fminf(mc[2 * q],     tlo);
                mc[2 * q + 1] = fminf(mc[2 * q + 1], thi);
            }
        }
#pragma unroll
        for (int q = 0; q < QPT; q++) {
            const int qj = qb * (NT * QPT) + q * NT + tid;
            g_tv [b][slice][qj] = fminf(mf[2 * q], mf[2 * q + 1]);
            g_tcv[b][slice][qj] = fminf(mc[2 * q], mc[2 * q + 1]);
        }
    } else {
        // ================= coarse -> target : partial min over one slice =================
        const int slice = bx - 128;
        const int base  = slice * SLICE;

        loadPairs(tXY, tZW, tgt, base, SLICE);

        ull qx2[2], qy2[2], qz2[2];
        float m[4];
#pragma unroll
        for (int q = 0; q < 2; q++) {
            const int ci = q * NT + tid;
            const float qx = crs[ci * 3 + 0];
            const float qy = crs[ci * 3 + 1];
            const float qz = crs[ci * 3 + 2];
            qx2[q] = pack2(qx, qx); qy2[q] = pack2(qy, qy); qz2[q] = pack2(qz, qz);
            m[2 * q] = 3.0e38f; m[2 * q + 1] = 3.0e38f;
        }
        const ull NEG2 = pack2(-2.0f, -2.0f);
        __syncthreads();

#pragma unroll 2
        for (int p = 0; p < SLICE / 2; p++) {
            const float4 vxy = tXY[p];
            const float4 vzw = tZW[p];
            const ull X2 = pack2(vxy.x, vxy.y);
            const ull Y2 = pack2(vxy.z, vxy.w);
            const ull Z2 = pack2(vzw.x, vzw.y);
            const ull W2 = pack2(vzw.z, vzw.w);
#pragma unroll
            for (int q = 0; q < 2; q++) {
                const ull xy2 = fma2(qz2[q], Z2, fma2(qy2[q], Y2, mul2(qx2[q], X2)));
                const ull t2  = fma2(NEG2, xy2, W2);
                float tlo, thi; unpack2(t2, tlo, thi);
                m[2 * q]     = fminf(m[2 * q],     tlo);
                m[2 * q + 1] = fminf(m[2 * q + 1], thi);
            }
        }
#pragma unroll
        for (int q = 0; q < 2; q++) {
            const int ci = q * NT + tid;
            g_cv[b][slice][ci] = fminf(m[2 * q], m[2 * q + 1]);
        }
    }
}

// Combine partial slices + per-query epilogue + block partial sums.
// Fine role additionally computes wedge-volume over the 254 interior triples
// of its 256-point window (boundary triples handled in tail_kernel).
// grid = (66, BB): bx<32 fine, [32,64) target, [64,66) coarse
__global__ void __launch_bounds__(NT) combine_kernel(const float* __restrict__ sc,
                                                     const float* __restrict__ sf,
                                                     const float* __restrict__ tp)
{
    __shared__ float sred[NT];
    __shared__ float sfin[NT][3], snt[NT][3];
    const int b   = blockIdx.y;
    const int bx  = blockIdx.x;
    const int tid = threadIdx.x;

    if (bx < 32) {
        const int qi = bx * NT + tid;
        // argmin across slices in ascending order (strict < keeps earliest)
        float best = g_av[b][0][qi]; int jb = g_ai[b][0][qi];
#pragma unroll
        for (int s = 1; s < NSL; s++) {
            const float v = g_av[b][s][qi];
            if (v < best) { best = v; jb = g_ai[b][s][qi]; }
        }
        const float* fin = sf + (size_t)b * NF * 3;
        const float* tgt = tp + (size_t)b * MM * 3;
        const float qx = fin[qi * 3 + 0];
        const float qy = fin[qi * 3 + 1];
        const float qz = fin[qi * 3 + 2];
        const float qq = qx * qx + qy * qy + qz * qz;

        const float d  = fmaxf(qq + best, 0.0f);
        const float d1 = sqrtf(fmaxf(d, EPSF));

        const float nx = tgt[jb * 3 + 0];
        const float ny = tgt[jb * 3 + 1];
        const float nz = tgt[jb * 3 + 2];
        const int o = (b * NF + qi) * 3;
        g_nt[o + 0] = nx; g_nt[o + 1] = ny; g_nt[o + 2] = nz;

        sfin[tid][0] = qx; sfin[tid][1] = qy; sfin[tid][2] = qz;
        snt [tid][0] = nx; snt [tid][1] = ny; snt [tid][2] = nz;

        const float yd = qy - ny;
        const float r0 = blockSum(d1,      sred);  // includes a __syncthreads barrier
        const float r1 = blockSum(qz * qz, sred);
        const float r2 = blockSum(nz * nz, sred);
        const float r3 = blockSum(yd * yd, sred);
        if (tid == 0) {
            g_pf[b][bx][0] = r0; g_pf[b][bx][1] = r1;
            g_pf[b][bx][2] = r2; g_pf[b][bx][3] = r3;
        }

        // interior wedge-volume triples (local rows tid, tid+1, tid+2)
        float vf = 0.0f, vn = 0.0f;
        if (tid < NT - 2) {
            float a0 = sfin[tid][0],   a1 = sfin[tid][1],   a2 = sfin[tid][2];
            float e0 = sfin[tid+1][0], e1 = sfin[tid+1][1], e2 = sfin[tid+1][2];
            float c0 = sfin[tid+2][0], c1 = sfin[tid+2][1], c2 = sfin[tid+2][2];
            float cx = a1 * e2 - a2 * e1;
            float cy = a2 * e0 - a0 * e2;
            float cz = a0 * e1 - a1 * e0;
            vf = cx * c0 + cy * c1 + cz * c2;

            a0 = snt[tid][0];   a1 = snt[tid][1];   a2 = snt[tid][2];
            e0 = snt[tid+1][0]; e1 = snt[tid+1][1]; e2 = snt[tid+1][2];
            c0 = snt[tid+2][0]; c1 = snt[tid+2][1]; c2 = snt[tid+2][2];
            cx = a1 * e2 - a2 * e1;
            cy = a2 * e0 - a0 * e2;
            cz = a0 * e1 - a1 * e0;
            vn = cx * c0 + cy * c1 + cz * c2;
        }
        const float r4 = blockSum(vf, sred);
        const float r5 = blockSum(vn, sred);
        if (tid == 0) { g_pv[b][bx][0] = r4; g_pv[b][bx][1] = r5; }
    } else if (bx < 64) {
        const int qj = (bx - 32) * NT + tid;
        float mF = g_tv[b][0][qj], mC = g_tcv[b][0][qj];
#pragma unroll
        for (int s = 1; s < NSL; s++) {
            mF = fminf(mF, g_tv[b][s][qj]);
            mC = fminf(mC, g_tcv[b][s][qj]);
        }
        const float* tgt = tp + (size_t)b * MM * 3;
        const float qx = tgt[qj * 3 + 0];
        const float qy = tgt[qj * 3 + 1];
        const float qz = tgt[qj * 3 + 2];
        const float qq = qx * qx + qy * qy + qz * qz;

        const float d2f = sqrtf(fmaxf(fmaxf(qq + mF, 0.0f), EPSF));
        const float d2c = sqrtf(fmaxf(fmaxf(qq + mC, 0.0f), EPSF));
        const float r0 = blockSum(d2f, sred);
        const float r1 = blockSum(d2c, sred);
        if (tid == 0) { g_pt[b][bx - 32][0] = r0; g_pt[b][bx - 32][1] = r1; }
    } else {
        const int ci = (bx - 64) * NT + tid;
        float m = g_cv[b][0][ci];
#pragma unroll
        for (int s = 1; s < NSL; s++) m = fminf(m, g_cv[b][s][ci]);

        const float* crs = sc + (size_t)b * NC * 3;
        const float qx = crs[ci * 3 + 0];
        const float qy = crs[ci * 3 + 1];
        const float qz = crs[ci * 3 + 2];
        const float qq = qx * qx + qy * qy + qz * qz;

        const float d1c = sqrtf(fmaxf(fmaxf(qq + m, 0.0f), EPSF));
        const float r0 = blockSum(d1c, sred);
        if (tid == 0) g_pc[b][bx - 64] = r0;
    }
}

// Tail: boundary wedge triples (the 2 per 256-block boundary that combine
// couldn't compute locally) + deterministic fixed-order combine of all partials.
__global__ void __launch_bounds__(NT) tail_kernel(const float* __restrict__ sf,
                                                  float* __restrict__ out)
{
    __shared__ float sred[NT];
    __shared__ float svol[BB][2];
    const int tid = threadIdx.x;

    for (int b = 0; b < BB; b++) {
        float vf = 0.0f, vn = 0.0f;
        // boundary triples: i = 256*k + 254, 256*k + 255 for k = 0..30  (62 triples)
        for (int t = tid; t < 62; t += NT) {
            const int k = t >> 1;
            const int i = 256 * k + 254 + (t & 1);
            const float* p = sf + (size_t)b * NF * 3 + (size_t)i * 3;
            float a0 = p[0], a1 = p[1], a2 = p[2];
            float e0 = p[3], e1 = p[4], e2 = p[5];
            float c0 = p[6], c1 = p[7], c2 = p[8];
            float cx = a1 * e2 - a2 * e1;
            float cy = a2 * e0 - a0 * e2;
            float cz = a0 * e1 - a1 * e0;
            vf += cx * c0 + cy * c1 + cz * c2;

            const float* q = g_nt + ((size_t)b * NF + i) * 3;
            a0 = q[0]; a1 = q[1]; a2 = q[2];
            e0 = q[3]; e1 = q[4]; e2 = q[5];
            c0 = q[6]; c1 = q[7]; c2 = q[8];
            cx = a1 * e2 - a2 * e1;
            cy = a2 * e0 - a0 * e2;
            cz = a0 * e1 - a1 * e0;
            vn += cx * c0 + cy * c1 + cz * c2;
        }
        const float r0 = blockSum(vf, sred);
        const float r1 = blockSum(vn, sred);
        if (tid == 0) { svol[b][0] = r0; svol[b][1] = r1; }
    }
    __syncthreads();

    if (tid == 0) {
        float S1f = 0.0f, Syd = 0.0f, S2f = 0.0f, S2c = 0.0f, S1c = 0.0f;
        float szf[BB], sznt[BB], vfb[BB], vnb[BB];
#pragma unroll
        for (int b = 0; b < BB; b++) { szf[b] = sznt[b] = 0.0f; vfb[b] = svol[b][0]; vnb[b] = svol[b][1]; }

        for (int b = 0; b < BB; b++) {
            for (int k = 0; k < 32; k++) {
                S1f     += g_pf[b][k][0];
                szf[b]  += g_pf[b][k][1];
                sznt[b] += g_pf[b][k][2];
                Syd     += g_pf[b][k][3];
                S2f     += g_pt[b][k][0];
                S2c     += g_pt[b][k][1];
                vfb[b]  += g_pv[b][k][0];
                vnb[b]  += g_pv[b][k][1];
            }
            S1c += g_pc[b][0] + g_pc[b][1];
        }

        const float la_f = 0.5f * (S1f / (float)(BB * NF) + S2f / (float)(BB * MM));
        const float la_c = 0.5f * (S1c / (float)(BB * NC) + S2c / (float)(BB * MM));
        const float lref = Syd / (float)(BB * NF);

        float lrot = 0.0f, lgeo = 0.0f;
        for (int b = 0; b < BB; b++) {
            const float dr = sqrtf(szf[b]) - sqrtf(sznt[b]);
            lrot += dr * dr;
            const float dg = (vfb[b] - vnb[b]) * (1.0f / 6.0f);
            lgeo += dg * dg;
        }
        lrot *= (1.0f / (float)BB);
        lgeo *= (1.0f / (float)BB);

        out[0] = lrot + lref + la_c + la_f + lgeo;
    }
}

extern "C" void kernel_launch(void* const* d_in, const int* in_sizes, int n_in,
                              void* d_out, int out_size)
{
    const float* sc = (const float*)d_in[0];  // source_coarse (B, 512, 3)
    const float* sf = (const float*)d_in[1];  // source_fine   (B, 8192, 3)
    const float* tp = (const float*)d_in[2];  // target_points (B, 8192, 3)
    float* out = (float*)d_out;

    dim3 g1(136, BB);
    nn_kernel<<<g1, NT>>>(sc, sf, tp);

    dim3 g2(66, BB);
    combine_kernel<<<g2, NT>>>(sc, sf, tp);

    tail_kernel<<<1, NT>>>(sf, out);
}

// round 10
// speedup vs baseline: 1.4956x; 1.1388x over previous
#include <cuda_runtime.h>
#include <math.h>

// Problem shapes (fixed by the dataset)
#define BB    2
#define NC    512
#define NF    8192
#define MM    8192
#define NT    256
#define SLICE 512       // targets per block slice
#define NSL   16        // slices (8192 / 512)
#define QPT   4         // queries per thread (main roles)
#define EPSF  1e-12f

typedef unsigned long long ull;

// ---------------- scratch (__device__ globals; no allocation allowed) ----------------
__device__ float g_av [BB][NSL][NF];     // fine->target partial min value per slice
__device__ int   g_ai [BB][NSL][NF];     // fine->target partial argmin index per slice
__device__ float g_tv [BB][NSL][MM];     // target->fine partial min per slice
__device__ float g_tcv[BB][NSL][MM];     // target->coarse partial min per coarse sub-slice
__device__ float g_cv [BB][NSL][NC];     // coarse->target partial min per slice
__device__ float g_nt [BB * NF * 3];     // gathered nearest target per fine point
__device__ float g_pf [BB][32][4];       // fine combine: sum d1, sum zf^2, sum znt^2, sum ydiff^2
__device__ float g_pt [BB][32][2];       // target combine: sum d2f, sum d2c
__device__ float g_pc [BB][2];           // coarse combine: sum d1c
__device__ float g_pv [BB][32][2];       // volume partials (interior triples): fine, new_target

// ---------------- packed f32x2 helpers (per-half bit-identical to scalar) ----------------
__device__ __forceinline__ ull pack2(float lo, float hi) {
    ull r; asm("mov.b64 %0, {%1, %2};" : "=l"(r) : "f"(lo), "f"(hi)); return r;
}
__device__ __forceinline__ void unpack2(ull v, float& lo, float& hi) {
    asm("mov.b64 {%0, %1}, %2;" : "=f"(lo), "=f"(hi) : "l"(v));
}
__device__ __forceinline__ ull mul2(ull a, ull b) {
    ull r; asm("mul.rn.f32x2 %0, %1, %2;" : "=l"(r) : "l"(a), "l"(b)); return r;
}
__device__ __forceinline__ ull fma2(ull a, ull b, ull c) {
    ull r; asm("fma.rn.f32x2 %0, %1, %2, %3;" : "=l"(r) : "l"(a), "l"(b), "l"(c)); return r;
}

// Deterministic in-block tree reduction
__device__ __forceinline__ float blockSum(float v, float* sh) {
    int t = threadIdx.x;
    sh[t] = v;
    __syncthreads();
#pragma unroll
    for (int s = NT / 2; s > 0; s >>= 1) {
        if (t < s) sh[t] += sh[t + s];
        __syncthreads();
    }
    float r = sh[0];
    __syncthreads();
    return r;
}

// Load `count` points (count even) starting at src[t0] into PRE-PACKED pair structs:
//   xy[p] = { pack(x_{2p},x_{2p+1}), pack(y_{2p},y_{2p+1}) }
//   zw[p] = { pack(z_{2p},z_{2p+1}), pack(w_{2p},w_{2p+1}) }   (w = |pt|^2)
// Hot loops then read one ulonglong2 (LDS.128) per operand pair — no pack MOVs.
__device__ __forceinline__ void loadPairs(ulonglong2* xy, ulonglong2* zw,
                                          const float* __restrict__ src,
                                          int t0, int count) {
    for (int p = threadIdx.x; p < count / 2; p += NT) {
        const int j0 = t0 + 2 * p;
        const float x0 = src[j0 * 3 + 0], y0 = src[j0 * 3 + 1], z0 = src[j0 * 3 + 2];
        const float x1 = src[j0 * 3 + 3], y1 = src[j0 * 3 + 4], z1 = src[j0 * 3 + 5];
        ulonglong2 a, b;
        a.x = pack2(x0, x1); a.y = pack2(y0, y1);
        b.x = pack2(z0, z1);
        b.y = pack2(x0 * x0 + y0 * y0 + z0 * z0,
                    x1 * x1 + y1 * y1 + z1 * z1);
        xy[p] = a; zw[p] = b;
    }
}

// Main pass: grid = (272, BB).
//  bx in [0,128):    fine->target argmin.  qblock = bx>>4, slice = bx&15
//  bx in [128,256):  target->fine min + target->coarse min. same decomposition
//  bx in [256,272):  coarse->target min. slice = bx-256, all 512 coarse queries (QPT=2)
__global__ void __launch_bounds__(NT) nn_kernel(const float* __restrict__ sc,
                                                const float* __restrict__ sf,
                                                const float* __restrict__ tp)
{
    __shared__ ulonglong2 tXY[SLICE / 2], tZW[SLICE / 2];
    __shared__ ulonglong2 cXY[16], cZW[16];   // coarse sub-slice (32 points)

    const int b   = blockIdx.y;
    const int bx  = blockIdx.x;
    const int tid = threadIdx.x;

    const float* tgt = tp + (size_t)b * MM * 3;
    const float* fin = sf + (size_t)b * NF * 3;
    const float* crs = sc + (size_t)b * NC * 3;

    if (bx < 128) {
        // ================= fine -> target : partial argmin over one slice =================
        const int qb    = bx >> 4;
        const int slice = bx & 15;
        const int base  = slice * SLICE;

        loadPairs(tXY, tZW, tgt, base, SLICE);

        ull qx2[QPT], qy2[QPT], qz2[QPT];
        float best[QPT];
        int   pb[QPT];
#pragma unroll
        for (int q = 0; q < QPT; q++) {
            const int qi = qb * (NT * QPT) + q * NT + tid;
            const float qx = fin[qi * 3 + 0];
            const float qy = fin[qi * 3 + 1];
            const float qz = fin[qi * 3 + 2];
            qx2[q] = pack2(qx, qx); qy2[q] = pack2(qy, qy); qz2[q] = pack2(qz, qz);
            best[q] = 3.0e38f; pb[q] = 0;
        }
        const ull NEG2 = pack2(-2.0f, -2.0f);
        __syncthreads();

#pragma unroll 4
        for (int p = 0; p < SLICE / 2; p++) {
            const ulonglong2 vxy = tXY[p];
            const ulonglong2 vzw = tZW[p];
#pragma unroll
            for (int q = 0; q < QPT; q++) {
                const ull xy2 = fma2(qz2[q], vzw.x, fma2(qy2[q], vxy.y, mul2(qx2[q], vxy.x)));
                const ull t2  = fma2(NEG2, xy2, vzw.y);
                float tlo, thi; unpack2(t2, tlo, thi);
                const float m = fminf(tlo, thi);
                if (m < best[q]) { best[q] = m; pb[q] = p; }
            }
        }
#pragma unroll
        for (int q = 0; q < QPT; q++) {
            const int qi = qb * (NT * QPT) + q * NT + tid;
            const int p = pb[q];
            const ulonglong2 vxy = tXY[p];
            const ulonglong2 vzw = tZW[p];
            const ull xy2 = fma2(qz2[q], vzw.x, fma2(qy2[q], vxy.y, mul2(qx2[q], vxy.x)));
            const ull t2  = fma2(NEG2, xy2, vzw.y);
            float tlo, thi; unpack2(t2, tlo, thi);
            const int jb = base + 2 * p + ((thi < tlo) ? 1 : 0);
            g_av[b][slice][qi] = best[q];
            g_ai[b][slice][qi] = jb;
        }
    } else if (bx < 256) {
        // ============ target -> fine (min) and target -> coarse (min), one slice ============
        const int r     = bx - 128;
        const int qb    = r >> 4;
        const int slice = r & 15;
        const int base  = slice * SLICE;

        loadPairs(tXY, tZW, fin, base, SLICE);
        loadPairs(cXY, cZW, crs, slice * 32, 32);

        ull qx2[QPT], qy2[QPT], qz2[QPT];
        float mf[QPT * 2], mc[QPT * 2];
#pragma unroll
        for (int q = 0; q < QPT; q++) {
            const int qj = qb * (NT * QPT) + q * NT + tid;
            const float qx = tgt[qj * 3 + 0];
            const float qy = tgt[qj * 3 + 1];
            const float qz = tgt[qj * 3 + 2];
            qx2[q] = pack2(qx, qx); qy2[q] = pack2(qy, qy); qz2[q] = pack2(qz, qz);
            mf[2 * q] = 3.0e38f; mf[2 * q + 1] = 3.0e38f;
            mc[2 * q] = 3.0e38f; mc[2 * q + 1] = 3.0e38f;
        }
        const ull NEG2 = pack2(-2.0f, -2.0f);
        __syncthreads();

#pragma unroll 4
        for (int p = 0; p < SLICE / 2; p++) {
            const ulonglong2 vxy = tXY[p];
            const ulonglong2 vzw = tZW[p];
#pragma unroll
            for (int q = 0; q < QPT; q++) {
                const ull xy2 = fma2(qz2[q], vzw.x, fma2(qy2[q], vxy.y, mul2(qx2[q], vxy.x)));
                const ull t2  = fma2(NEG2, xy2, vzw.y);
                float tlo, thi; unpack2(t2, tlo, thi);
                mf[2 * q]     = fminf(mf[2 * q],     tlo);
                mf[2 * q + 1] = fminf(mf[2 * q + 1], thi);
            }
        }
#pragma unroll
        for (int p = 0; p < 16; p++) {
            const ulonglong2 vxy = cXY[p];
            const ulonglong2 vzw = cZW[p];
#pragma unroll
            for (int q = 0; q < QPT; q++) {
                const ull xy2 = fma2(qz2[q], vzw.x, fma2(qy2[q], vxy.y, mul2(qx2[q], vxy.x)));
                const ull t2  = fma2(NEG2, xy2, vzw.y);
                float tlo, thi; unpack2(t2, tlo, thi);
                mc[2 * q]     = fminf(mc[2 * q],     tlo);
                mc[2 * q + 1] = fminf(mc[2 * q + 1], thi);
            }
        }
#pragma unroll
        for (int q = 0; q < QPT; q++) {
            const int qj = qb * (NT * QPT) + q * NT + tid;
            g_tv [b][slice][qj] = fminf(mf[2 * q], mf[2 * q + 1]);
            g_tcv[b][slice][qj] = fminf(mc[2 * q], mc[2 * q + 1]);
        }
    } else {
        // ================= coarse -> target : partial min over one slice =================
        const int slice = bx - 256;
        const int base  = slice * SLICE;

        loadPairs(tXY, tZW, tgt, base, SLICE);

        ull qx2[2], qy2[2], qz2[2];
        float m[4];
#pragma unroll
        for (int q = 0; q < 2; q++) {
            const int ci = q * NT + tid;
            const float qx = crs[ci * 3 + 0];
            const float qy = crs[ci * 3 + 1];
            const float qz = crs[ci * 3 + 2];
            qx2[q] = pack2(qx, qx); qy2[q] = pack2(qy, qy); qz2[q] = pack2(qz, qz);
            m[2 * q] = 3.0e38f; m[2 * q + 1] = 3.0e38f;
        }
        const ull NEG2 = pack2(-2.0f, -2.0f);
        __syncthreads();

#pragma unroll 4
        for (int p = 0; p < SLICE / 2; p++) {
            const ulonglong2 vxy = tXY[p];
            const ulonglong2 vzw = tZW[p];
#pragma unroll
            for (int q = 0; q < 2; q++) {
                const ull xy2 = fma2(qz2[q], vzw.x, fma2(qy2[q], vxy.y, mul2(qx2[q], vxy.x)));
                const ull t2  = fma2(NEG2, xy2, vzw.y);
                float tlo, thi; unpack2(t2, tlo, thi);
                m[2 * q]     = fminf(m[2 * q],     tlo);
                m[2 * q + 1] = fminf(m[2 * q + 1], thi);
            }
        }
#pragma unroll
        for (int q = 0; q < 2; q++) {
            const int ci = q * NT + tid;
            g_cv[b][slice][ci] = fminf(m[2 * q], m[2 * q + 1]);
        }
    }
}

// Combine partial slices + per-query epilogue + block partial sums.
// Fine role additionally computes wedge-volume over the 254 interior triples
// of its 256-point window (boundary triples handled in tail_kernel).
// grid = (66, BB): bx<32 fine, [32,64) target, [64,66) coarse
__global__ void __launch_bounds__(NT) combine_kernel(const float* __restrict__ sc,
                                                     const float* __restrict__ sf,
                                                     const float* __restrict__ tp)
{
    __shared__ float sred[NT];
    __shared__ float sfin[NT][3], snt[NT][3];
    const int b   = blockIdx.y;
    const int bx  = blockIdx.x;
    const int tid = threadIdx.x;

    if (bx < 32) {
        const int qi = bx * NT + tid;
        // argmin across slices in ascending order (strict < keeps earliest)
        float best = g_av[b][0][qi]; int jb = g_ai[b][0][qi];
#pragma unroll
        for (int s = 1; s < NSL; s++) {
            const float v = g_av[b][s][qi];
            if (v < best) { best = v; jb = g_ai[b][s][qi]; }
        }
        const float* fin = sf + (size_t)b * NF * 3;
        const float* tgt = tp + (size_t)b * MM * 3;
        const float qx = fin[qi * 3 + 0];
        const float qy = fin[qi * 3 + 1];
        const float qz = fin[qi * 3 + 2];
        const float qq = qx * qx + qy * qy + qz * qz;

        const float d  = fmaxf(qq + best, 0.0f);
        const float d1 = sqrtf(fmaxf(d, EPSF));

        const float nx = tgt[jb * 3 + 0];
        const float ny = tgt[jb * 3 + 1];
        const float nz = tgt[jb * 3 + 2];
        const int o = (b * NF + qi) * 3;
        g_nt[o + 0] = nx; g_nt[o + 1] = ny; g_nt[o + 2] = nz;

        sfin[tid][0] = qx; sfin[tid][1] = qy; sfin[tid][2] = qz;
        snt [tid][0] = nx; snt [tid][1] = ny; snt [tid][2] = nz;

        const float yd = qy - ny;
        const float r0 = blockSum(d1,      sred);
        const float r1 = blockSum(qz * qz, sred);
        const float r2 = blockSum(nz * nz, sred);
        const float r3 = blockSum(yd * yd, sred);
        if (tid == 0) {
            g_pf[b][bx][0] = r0; g_pf[b][bx][1] = r1;
            g_pf[b][bx][2] = r2; g_pf[b][bx][3] = r3;
        }

        // interior wedge-volume triples (local rows tid, tid+1, tid+2)
        float vf = 0.0f, vn = 0.0f;
        if (tid < NT - 2) {
            float a0 = sfin[tid][0],   a1 = sfin[tid][1],   a2 = sfin[tid][2];
            float e0 = sfin[tid+1][0], e1 = sfin[tid+1][1], e2 = sfin[tid+1][2];
            float c0 = sfin[tid+2][0], c1 = sfin[tid+2][1], c2 = sfin[tid+2][2];
            float cx = a1 * e2 - a2 * e1;
            float cy = a2 * e0 - a0 * e2;
            float cz = a0 * e1 - a1 * e0;
            vf = cx * c0 + cy * c1 + cz * c2;

            a0 = snt[tid][0];   a1 = snt[tid][1];   a2 = snt[tid][2];
            e0 = snt[tid+1][0]; e1 = snt[tid+1][1]; e2 = snt[tid+1][2];
            c0 = snt[tid+2][0]; c1 = snt[tid+2][1]; c2 = snt[tid+2][2];
            cx = a1 * e2 - a2 * e1;
            cy = a2 * e0 - a0 * e2;
            cz = a0 * e1 - a1 * e0;
            vn = cx * c0 + cy * c1 + cz * c2;
        }
        const float r4 = blockSum(vf, sred);
        const float r5 = blockSum(vn, sred);
        if (tid == 0) { g_pv[b][bx][0] = r4; g_pv[b][bx][1] = r5; }
    } else if (bx < 64) {
        const int qj = (bx - 32) * NT + tid;
        float mF = g_tv[b][0][qj], mC = g_tcv[b][0][qj];
#pragma unroll
        for (int s = 1; s < NSL; s++) {
            mF = fminf(mF, g_tv[b][s][qj]);
            mC = fminf(mC, g_tcv[b][s][qj]);
        }
        const float* tgt = tp + (size_t)b * MM * 3;
        const float qx = tgt[qj * 3 + 0];
        const float qy = tgt[qj * 3 + 1];
        const float qz = tgt[qj * 3 + 2];
        const float qq = qx * qx + qy * qy + qz * qz;

        const float d2f = sqrtf(fmaxf(fmaxf(qq + mF, 0.0f), EPSF));
        const float d2c = sqrtf(fmaxf(fmaxf(qq + mC, 0.0f), EPSF));
        const float r0 = blockSum(d2f, sred);
        const float r1 = blockSum(d2c, sred);
        if (tid == 0) { g_pt[b][bx - 32][0] = r0; g_pt[b][bx - 32][1] = r1; }
    } else {
        const int ci = (bx - 64) * NT + tid;
        float m = g_cv[b][0][ci];
#pragma unroll
        for (int s = 1; s < NSL; s++) m = fminf(m, g_cv[b][s][ci]);

        const float* crs = sc + (size_t)b * NC * 3;
        const float qx = crs[ci * 3 + 0];
        const float qy = crs[ci * 3 + 1];
        const float qz = crs[ci * 3 + 2];
        const float qq = qx * qx + qy * qy + qz * qz;

        const float d1c = sqrtf(fmaxf(fmaxf(qq + m, 0.0f), EPSF));
        const float r0 = blockSum(d1c, sred);
        if (tid == 0) g_pc[b][bx - 64] = r0;
    }
}

// Tail: boundary wedge triples + deterministic fixed-order combine of all partials.
__global__ void __launch_bounds__(NT) tail_kernel(const float* __restrict__ sf,
                                                  float* __restrict__ out)
{
    __shared__ float sred[NT];
    __shared__ float svol[BB][2];
    const int tid = threadIdx.x;

    for (int b = 0; b < BB; b++) {
        float vf = 0.0f, vn = 0.0f;
        // boundary triples: i = 256*k + 254, 256*k + 255 for k = 0..30  (62 triples)
        for (int t = tid; t < 62; t += NT) {
            const int k = t >> 1;
            const int i = 256 * k + 254 + (t & 1);
            const float* p = sf + (size_t)b * NF * 3 + (size_t)i * 3;
            float a0 = p[0], a1 = p[1], a2 = p[2];
            float e0 = p[3], e1 = p[4], e2 = p[5];
            float c0 = p[6], c1 = p[7], c2 = p[8];
            float cx = a1 * e2 - a2 * e1;
            float cy = a2 * e0 - a0 * e2;
            float cz = a0 * e1 - a1 * e0;
            vf += cx * c0 + cy * c1 + cz * c2;

            const float* q = g_nt + ((size_t)b * NF + i) * 3;
            a0 = q[0]; a1 = q[1]; a2 = q[2];
            e0 = q[3]; e1 = q[4]; e2 = q[5];
            c0 = q[6]; c1 = q[7]; c2 = q[8];
            cx = a1 * e2 - a2 * e1;
            cy = a2 * e0 - a0 * e2;
            cz = a0 * e1 - a1 * e0;
            vn += cx * c0 + cy * c1 + cz * c2;
        }
        const float r0 = blockSum(vf, sred);
        const float r1 = blockSum(vn, sred);
        if (tid == 0) { svol[b][0] = r0; svol[b][1] = r1; }
    }
    __syncthreads();

    if (tid == 0) {
        float S1f = 0.0f, Syd = 0.0f, S2f = 0.0f, S2c = 0.0f, S1c = 0.0f;
        float szf[BB], sznt[BB], vfb[BB], vnb[BB];
#pragma unroll
        for (int b = 0; b < BB; b++) { szf[b] = sznt[b] = 0.0f; vfb[b] = svol[b][0]; vnb[b] = svol[b][1]; }

        for (int b = 0; b < BB; b++) {
            for (int k = 0; k < 32; k++) {
                S1f     += g_pf[b][k][0];
                szf[b]  += g_pf[b][k][1];
                sznt[b] += g_pf[b][k][2];
                Syd     += g_pf[b][k][3];
                S2f     += g_pt[b][k][0];
                S2c     += g_pt[b][k][1];
                vfb[b]  += g_pv[b][k][0];
                vnb[b]  += g_pv[b][k][1];
            }
            S1c += g_pc[b][0] + g_pc[b][1];
        }

        const float la_f = 0.5f * (S1f / (float)(BB * NF) + S2f / (float)(BB * MM));
        const float la_c = 0.5f * (S1c / (float)(BB * NC) + S2c / (float)(BB * MM));
        const float lref = Syd / (float)(BB * NF);

        float lrot = 0.0f, lgeo = 0.0f;
        for (int b = 0; b < BB; b++) {
            const float dr = sqrtf(szf[b]) - sqrtf(sznt[b]);
            lrot += dr * dr;
            const float dg = (vfb[b] - vnb[b]) * (1.0f / 6.0f);
            lgeo += dg * dg;
        }
        lrot *= (1.0f / (float)BB);
        lgeo *= (1.0f / (float)BB);

        out[0] = lrot + lref + la_c + la_f + lgeo;
    }
}

extern "C" void kernel_launch(void* const* d_in, const int* in_sizes, int n_in,
                              void* d_out, int out_size)
{
    const float* sc = (const float*)d_in[0];  // source_coarse (B, 512, 3)
    const float* sf = (const float*)d_in[1];  // source_fine   (B, 8192, 3)
    const float* tp = (const float*)d_in[2];  // target_points (B, 8192, 3)
    float* out = (float*)d_out;

    dim3 g1(272, BB);
    nn_kernel<<<g1, NT>>>(sc, sf, tp);

    dim3 g2(66, BB);
    combine_kernel<<<g2, NT>>>(sc, sf, tp);

    tail_kernel<<<1, NT>>>(sf, out);
}

// round 11
// speedup vs baseline: 1.5089x; 1.0089x over previous
#include <cuda_runtime.h>
#include <math.h>

// Problem shapes (fixed by the dataset)
#define BB    2
#define NC    512
#define NF    8192
#define MM    8192
#define NT    256
#define SLICE 512       // targets per block slice
#define NSL   16        // slices (8192 / 512)
#define QPT   4         // queries per thread (main roles)
#define EPSF  1e-12f

typedef unsigned long long ull;

// ---------------- scratch (__device__ globals; no allocation allowed) ----------------
__device__ float g_av [BB][NSL][NF];     // fine->target partial min value per slice
__device__ int   g_ai [BB][NSL][NF];     // fine->target partial argmin index per slice
__device__ float g_tv [BB][NSL][MM];     // target->fine partial min per slice
__device__ float g_tcv[BB][NSL][MM];     // target->coarse partial min per coarse sub-slice
__device__ float g_cv [BB][NSL][NC];     // coarse->target partial min per slice
__device__ float g_nt [BB * NF * 3];     // gathered nearest target per fine point
__device__ float g_pf [BB][32][4];       // fine combine: sum d1, sum zf^2, sum znt^2, sum ydiff^2
__device__ float g_pt [BB][32][2];       // target combine: sum d2f, sum d2c
__device__ float g_pc [BB][2];           // coarse combine: sum d1c
__device__ float g_pv [BB][32][2];       // volume partials (interior triples): fine, new_target
__device__ unsigned int g_ticket;        // last-block ticket (wraps to 0 each launch)

// ---------------- packed f32x2 helpers (per-half bit-identical to scalar) ----------------
__device__ __forceinline__ ull pack2(float lo, float hi) {
    ull r; asm("mov.b64 %0, {%1, %2};" : "=l"(r) : "f"(lo), "f"(hi)); return r;
}
__device__ __forceinline__ void unpack2(ull v, float& lo, float& hi) {
    asm("mov.b64 {%0, %1}, %2;" : "=f"(lo), "=f"(hi) : "l"(v));
}
__device__ __forceinline__ ull mul2(ull a, ull b) {
    ull r; asm("mul.rn.f32x2 %0, %1, %2;" : "=l"(r) : "l"(a), "l"(b)); return r;
}
__device__ __forceinline__ ull fma2(ull a, ull b, ull c) {
    ull r; asm("fma.rn.f32x2 %0, %1, %2, %3;" : "=l"(r) : "l"(a), "l"(b), "l"(c)); return r;
}

// Deterministic in-block tree reduction
__device__ __forceinline__ float blockSum(float v, float* sh) {
    int t = threadIdx.x;
    sh[t] = v;
    __syncthreads();
#pragma unroll
    for (int s = NT / 2; s > 0; s >>= 1) {
        if (t < s) sh[t] += sh[t + s];
        __syncthreads();
    }
    float r = sh[0];
    __syncthreads();
    return r;
}

// RAW pairs (argmin role — arithmetic must match the verified form exactly):
//   xy[p] = { pack(x0,x1), pack(y0,y1) },  zw[p] = { pack(z0,z1), pack(w0,w1) }
__device__ __forceinline__ void loadPairsRaw(ulonglong2* xy, ulonglong2* zw,
                                             const float* __restrict__ src,
                                             int t0, int count) {
    for (int p = threadIdx.x; p < count / 2; p += NT) {
        const int j0 = t0 + 2 * p;
        const float x0 = src[j0 * 3 + 0], y0 = src[j0 * 3 + 1], z0 = src[j0 * 3 + 2];
        const float x1 = src[j0 * 3 + 3], y1 = src[j0 * 3 + 4], z1 = src[j0 * 3 + 5];
        ulonglong2 a, b;
        a.x = pack2(x0, x1); a.y = pack2(y0, y1);
        b.x = pack2(z0, z1);
        b.y = pack2(x0 * x0 + y0 * y0 + z0 * z0,
                    x1 * x1 + y1 * y1 + z1 * z1);
        xy[p] = a; zw[p] = b;
    }
}

// SCALED pairs (min-only roles): store (-2x, -2y, -2z, |p|^2) so the distance is
// 3 fma2 ops: t = fma(qx,-2x, fma(qy,-2y, fma(qz,-2z, w))). Reassociation only
// perturbs min-distance sums by ~1 ulp (no argmin depends on these roles).
__device__ __forceinline__ void loadPairsScaled(ulonglong2* xy, ulonglong2* zw,
                                                const float* __restrict__ src,
                                                int t0, int count) {
    for (int p = threadIdx.x; p < count / 2; p += NT) {
        const int j0 = t0 + 2 * p;
        const float x0 = src[j0 * 3 + 0], y0 = src[j0 * 3 + 1], z0 = src[j0 * 3 + 2];
        const float x1 = src[j0 * 3 + 3], y1 = src[j0 * 3 + 4], z1 = src[j0 * 3 + 5];
        ulonglong2 a, b;
        a.x = pack2(-2.0f * x0, -2.0f * x1);
        a.y = pack2(-2.0f * y0, -2.0f * y1);
        b.x = pack2(-2.0f * z0, -2.0f * z1);
        b.y = pack2(x0 * x0 + y0 * y0 + z0 * z0,
                    x1 * x1 + y1 * y1 + z1 * z1);
        xy[p] = a; zw[p] = b;
    }
}

// Main pass: grid = (272, BB).
//  bx in [0,128):    fine->target argmin.  qblock = bx>>4, slice = bx&15
//  bx in [128,256):  target->fine min + target->coarse min. same decomposition
//  bx in [256,272):  coarse->target min. slice = bx-256, all 512 coarse queries (QPT=2)
__global__ void __launch_bounds__(NT) nn_kernel(const float* __restrict__ sc,
                                                const float* __restrict__ sf,
                                                const float* __restrict__ tp)
{
    __shared__ ulonglong2 tXY[SLICE / 2], tZW[SLICE / 2];
    __shared__ ulonglong2 cXY[16], cZW[16];   // coarse sub-slice (32 points)

    const int b   = blockIdx.y;
    const int bx  = blockIdx.x;
    const int tid = threadIdx.x;

    const float* tgt = tp + (size_t)b * MM * 3;
    const float* fin = sf + (size_t)b * NF * 3;
    const float* crs = sc + (size_t)b * NC * 3;

    if (bx < 128) {
        // ================= fine -> target : partial argmin over one slice =================
        // EXACT verified arithmetic: xy=fma(qz,z,fma(qy,y,qx*x)); t=fma(-2,xy,w)
        const int qb    = bx >> 4;
        const int slice = bx & 15;
        const int base  = slice * SLICE;

        loadPairsRaw(tXY, tZW, tgt, base, SLICE);

        ull qx2[QPT], qy2[QPT], qz2[QPT];
        float best[QPT];
        int   pb[QPT];
#pragma unroll
        for (int q = 0; q < QPT; q++) {
            const int qi = qb * (NT * QPT) + q * NT + tid;
            const float qx = fin[qi * 3 + 0];
            const float qy = fin[qi * 3 + 1];
            const float qz = fin[qi * 3 + 2];
            qx2[q] = pack2(qx, qx); qy2[q] = pack2(qy, qy); qz2[q] = pack2(qz, qz);
            best[q] = 3.0e38f; pb[q] = 0;
        }
        const ull NEG2 = pack2(-2.0f, -2.0f);
        __syncthreads();

#pragma unroll 4
        for (int p = 0; p < SLICE / 2; p++) {
            const ulonglong2 vxy = tXY[p];
            const ulonglong2 vzw = tZW[p];
#pragma unroll
            for (int q = 0; q < QPT; q++) {
                const ull xy2 = fma2(qz2[q], vzw.x, fma2(qy2[q], vxy.y, mul2(qx2[q], vxy.x)));
                const ull t2  = fma2(NEG2, xy2, vzw.y);
                float tlo, thi; unpack2(t2, tlo, thi);
                const float m = fminf(tlo, thi);
                if (m < best[q]) { best[q] = m; pb[q] = p; }
            }
        }
#pragma unroll
        for (int q = 0; q < QPT; q++) {
            const int qi = qb * (NT * QPT) + q * NT + tid;
            const int p = pb[q];
            const ulonglong2 vxy = tXY[p];
            const ulonglong2 vzw = tZW[p];
            const ull xy2 = fma2(qz2[q], vzw.x, fma2(qy2[q], vxy.y, mul2(qx2[q], vxy.x)));
            const ull t2  = fma2(NEG2, xy2, vzw.y);
            float tlo, thi; unpack2(t2, tlo, thi);
            const int jb = base + 2 * p + ((thi < tlo) ? 1 : 0);
            g_av[b][slice][qi] = best[q];
            g_ai[b][slice][qi] = jb;
        }
    } else if (bx < 256) {
        // ============ target -> fine (min) and target -> coarse (min), one slice ============
        const int r     = bx - 128;
        const int qb    = r >> 4;
        const int slice = r & 15;
        const int base  = slice * SLICE;

        loadPairsScaled(tXY, tZW, fin, base, SLICE);
        loadPairsScaled(cXY, cZW, crs, slice * 32, 32);

        ull qx2[QPT], qy2[QPT], qz2[QPT];
        float mf[QPT * 2], mc[QPT * 2];
#pragma unroll
        for (int q = 0; q < QPT; q++) {
            const int qj = qb * (NT * QPT) + q * NT + tid;
            const float qx = tgt[qj * 3 + 0];
            const float qy = tgt[qj * 3 + 1];
            const float qz = tgt[qj * 3 + 2];
            qx2[q] = pack2(qx, qx); qy2[q] = pack2(qy, qy); qz2[q] = pack2(qz, qz);
            mf[2 * q] = 3.0e38f; mf[2 * q + 1] = 3.0e38f;
            mc[2 * q] = 3.0e38f; mc[2 * q + 1] = 3.0e38f;
        }
        __syncthreads();

#pragma unroll 4
        for (int p = 0; p < SLICE / 2; p++) {
            const ulonglong2 vxy = tXY[p];
            const ulonglong2 vzw = tZW[p];
#pragma unroll
            for (int q = 0; q < QPT; q++) {
                const ull t2 = fma2(qx2[q], vxy.x, fma2(qy2[q], vxy.y, fma2(qz2[q], vzw.x, vzw.y)));
                float tlo, thi; unpack2(t2, tlo, thi);
                mf[2 * q]     = fminf(mf[2 * q],     tlo);
                mf[2 * q + 1] = fminf(mf[2 * q + 1], thi);
            }
        }
#pragma unroll
        for (int p = 0; p < 16; p++) {
            const ulonglong2 vxy = cXY[p];
            const ulonglong2 vzw = cZW[p];
#pragma unroll
            for (int q = 0; q < QPT; q++) {
                const ull t2 = fma2(qx2[q], vxy.x, fma2(qy2[q], vxy.y, fma2(qz2[q], vzw.x, vzw.y)));
                float tlo, thi; unpack2(t2, tlo, thi);
                mc[2 * q]     = fminf(mc[2 * q],     tlo);
                mc[2 * q + 1] = fminf(mc[2 * q + 1], thi);
            }
        }
#pragma unroll
        for (int q = 0; q < QPT; q++) {
            const int qj = qb * (NT * QPT) + q * NT + tid;
            g_tv [b][slice][qj] = fminf(mf[2 * q], mf[2 * q + 1]);
            g_tcv[b][slice][qj] = fminf(mc[2 * q], mc[2 * q + 1]);
        }
    } else {
        // ================= coarse -> target : partial min over one slice =================
        const int slice = bx - 256;
        const int base  = slice * SLICE;

        loadPairsScaled(tXY, tZW, tgt, base, SLICE);

        ull qx2[2], qy2[2], qz2[2];
        float m[4];
#pragma unroll
        for (int q = 0; q < 2; q++) {
            const int ci = q * NT + tid;
            const float qx = crs[ci * 3 + 0];
            const float qy = crs[ci * 3 + 1];
            const float qz = crs[ci * 3 + 2];
            qx2[q] = pack2(qx, qx); qy2[q] = pack2(qy, qy); qz2[q] = pack2(qz, qz);
            m[2 * q] = 3.0e38f; m[2 * q + 1] = 3.0e38f;
        }
        __syncthreads();

#pragma unroll 4
        for (int p = 0; p < SLICE / 2; p++) {
            const ulonglong2 vxy = tXY[p];
            const ulonglong2 vzw = tZW[p];
#pragma unroll
            for (int q = 0; q < 2; q++) {
                const ull t2 = fma2(qx2[q], vxy.x, fma2(qy2[q], vxy.y, fma2(qz2[q], vzw.x, vzw.y)));
                float tlo, thi; unpack2(t2, tlo, thi);
                m[2 * q]     = fminf(m[2 * q],     tlo);
                m[2 * q + 1] = fminf(m[2 * q + 1], thi);
            }
        }
#pragma unroll
        for (int q = 0; q < 2; q++) {
            const int ci = q * NT + tid;
            g_cv[b][slice][ci] = fminf(m[2 * q], m[2 * q + 1]);
        }
    }
}

// Combine + fused tail. grid = (66, BB) -> 132 blocks; the LAST block to finish
// (atomicInc ticket, wraps to 0 for graph replay) runs the boundary volume
// triples and the deterministic fixed-order finalize.
__global__ void __launch_bounds__(NT) combine_kernel(const float* __restrict__ sc,
                                                     const float* __restrict__ sf,
                                                     const float* __restrict__ tp,
                                                     float* __restrict__ out)
{
    __shared__ float sred[NT];
    __shared__ float sfin[NT][3], snt[NT][3];
    __shared__ bool  s_last;
    const int b   = blockIdx.y;
    const int bx  = blockIdx.x;
    const int tid = threadIdx.x;

    if (bx < 32) {
        const int qi = bx * NT + tid;
        // argmin across slices in ascending order (strict < keeps earliest)
        float best = g_av[b][0][qi]; int jb = g_ai[b][0][qi];
#pragma unroll
        for (int s = 1; s < NSL; s++) {
            const float v = g_av[b][s][qi];
            if (v < best) { best = v; jb = g_ai[b][s][qi]; }
        }
        const float* fin = sf + (size_t)b * NF * 3;
        const float* tgt = tp + (size_t)b * MM * 3;
        const float qx = fin[qi * 3 + 0];
        const float qy = fin[qi * 3 + 1];
        const float qz = fin[qi * 3 + 2];
        const float qq = qx * qx + qy * qy + qz * qz;

        const float d  = fmaxf(qq + best, 0.0f);
        const float d1 = sqrtf(fmaxf(d, EPSF));

        const float nx = tgt[jb * 3 + 0];
        const float ny = tgt[jb * 3 + 1];
        const float nz = tgt[jb * 3 + 2];
        const int o = (b * NF + qi) * 3;
        g_nt[o + 0] = nx; g_nt[o + 1] = ny; g_nt[o + 2] = nz;

        sfin[tid][0] = qx; sfin[tid][1] = qy; sfin[tid][2] = qz;
        snt [tid][0] = nx; snt [tid][1] = ny; snt [tid][2] = nz;

        const float yd = qy - ny;
        const float r0 = blockSum(d1,      sred);
        const float r1 = blockSum(qz * qz, sred);
        const float r2 = blockSum(nz * nz, sred);
        const float r3 = blockSum(yd * yd, sred);
        if (tid == 0) {
            g_pf[b][bx][0] = r0; g_pf[b][bx][1] = r1;
            g_pf[b][bx][2] = r2; g_pf[b][bx][3] = r3;
        }

        // interior wedge-volume triples (local rows tid, tid+1, tid+2)
        float vf = 0.0f, vn = 0.0f;
        if (tid < NT - 2) {
            float a0 = sfin[tid][0],   a1 = sfin[tid][1],   a2 = sfin[tid][2];
            float e0 = sfin[tid+1][0], e1 = sfin[tid+1][1], e2 = sfin[tid+1][2];
            float c0 = sfin[tid+2][0], c1 = sfin[tid+2][1], c2 = sfin[tid+2][2];
            float cx = a1 * e2 - a2 * e1;
            float cy = a2 * e0 - a0 * e2;
            float cz = a0 * e1 - a1 * e0;
            vf = cx * c0 + cy * c1 + cz * c2;

            a0 = snt[tid][0];   a1 = snt[tid][1];   a2 = snt[tid][2];
            e0 = snt[tid+1][0]; e1 = snt[tid+1][1]; e2 = snt[tid+1][2];
            c0 = snt[tid+2][0]; c1 = snt[tid+2][1]; c2 = snt[tid+2][2];
            cx = a1 * e2 - a2 * e1;
            cy = a2 * e0 - a0 * e2;
            cz = a0 * e1 - a1 * e0;
            vn = cx * c0 + cy * c1 + cz * c2;
        }
        const float r4 = blockSum(vf, sred);
        const float r5 = blockSum(vn, sred);
        if (tid == 0) { g_pv[b][bx][0] = r4; g_pv[b][bx][1] = r5; }
    } else if (bx < 64) {
        const int qj = (bx - 32) * NT + tid;
        float mF = g_tv[b][0][qj], mC = g_tcv[b][0][qj];
#pragma unroll
        for (int s = 1; s < NSL; s++) {
            mF = fminf(mF, g_tv[b][s][qj]);
            mC = fminf(mC, g_tcv[b][s][qj]);
        }
        const float* tgt = tp + (size_t)b * MM * 3;
        const float qx = tgt[qj * 3 + 0];
        const float qy = tgt[qj * 3 + 1];
        const float qz = tgt[qj * 3 + 2];
        const float qq = qx * qx + qy * qy + qz * qz;

        const float d2f = sqrtf(fmaxf(fmaxf(qq + mF, 0.0f), EPSF));
        const float d2c = sqrtf(fmaxf(fmaxf(qq + mC, 0.0f), EPSF));
        const float r0 = blockSum(d2f, sred);
        const float r1 = blockSum(d2c, sred);
        if (tid == 0) { g_pt[b][bx - 32][0] = r0; g_pt[b][bx - 32][1] = r1; }
    } else {
        const int ci = (bx - 64) * NT + tid;
        float m = g_cv[b][0][ci];
#pragma unroll
        for (int s = 1; s < NSL; s++) m = fminf(m, g_cv[b][s][ci]);

        const float* crs = sc + (size_t)b * NC * 3;
        const float qx = crs[ci * 3 + 0];
        const float qy = crs[ci * 3 + 1];
        const float qz = crs[ci * 3 + 2];
        const float qq = qx * qx + qy * qy + qz * qz;

        const float d1c = sqrtf(fmaxf(fmaxf(qq + m, 0.0f), EPSF));
        const float r0 = blockSum(d1c, sred);
        if (tid == 0) g_pc[b][bx - 64] = r0;
    }

    // ---------------- last-block fused tail ----------------
    __threadfence();                       // make this block's partials visible
    if (tid == 0) {
        const unsigned int total = 66 * BB;
        // atomicInc wraps to 0 after the last block -> self-resetting for graph replay
        const unsigned int old = atomicInc(&g_ticket, total - 1);
        s_last = (old == total - 1);
    }
    __syncthreads();
    if (!s_last) return;
    // All other blocks' writes are fenced-before-arrival -> visible here.

    __shared__ float svol[BB][2];
    for (int bb = 0; bb < BB; bb++) {
        float vf = 0.0f, vn = 0.0f;
        // boundary triples: i = 256*k + 254, 256*k + 255 for k = 0..30  (62 triples)
        for (int t = tid; t < 62; t += NT) {
            const int k = t >> 1;
            const int i = 256 * k + 254 + (t & 1);
            const float* p = sf + (size_t)bb * NF * 3 + (size_t)i * 3;
            float a0 = p[0], a1 = p[1], a2 = p[2];
            float e0 = p[3], e1 = p[4], e2 = p[5];
            float c0 = p[6], c1 = p[7], c2 = p[8];
            float cx = a1 * e2 - a2 * e1;
            float cy = a2 * e0 - a0 * e2;
            float cz = a0 * e1 - a1 * e0;
            vf += cx * c0 + cy * c1 + cz * c2;

            const float* q = g_nt + ((size_t)bb * NF + i) * 3;
            a0 = q[0]; a1 = q[1]; a2 = q[2];
            e0 = q[3]; e1 = q[4]; e2 = q[5];
            c0 = q[6]; c1 = q[7]; c2 = q[8];
            cx = a1 * e2 - a2 * e1;
            cy = a2 * e0 - a0 * e2;
            cz = a0 * e1 - a1 * e0;
            vn += cx * c0 + cy * c1 + cz * c2;
        }
        const float r0 = blockSum(vf, sred);
        const float r1 = blockSum(vn, sred);
        if (tid == 0) { svol[bb][0] = r0; svol[bb][1] = r1; }
    }
    __syncthreads();

    if (tid == 0) {
        float S1f = 0.0f, Syd = 0.0f, S2f = 0.0f, S2c = 0.0f, S1c = 0.0f;
        float szf[BB], sznt[BB], vfb[BB], vnb[BB];
#pragma unroll
        for (int bb = 0; bb < BB; bb++) {
            szf[bb] = sznt[bb] = 0.0f;
            vfb[bb] = svol[bb][0]; vnb[bb] = svol[bb][1];
        }

        for (int bb = 0; bb < BB; bb++) {
            for (int k = 0; k < 32; k++) {
                S1f      += g_pf[bb][k][0];
                szf[bb]  += g_pf[bb][k][1];
                sznt[bb] += g_pf[bb][k][2];
                Syd      += g_pf[bb][k][3];
                S2f      += g_pt[bb][k][0];
                S2c      += g_pt[bb][k][1];
                vfb[bb]  += g_pv[bb][k][0];
                vnb[bb]  += g_pv[bb][k][1];
            }
            S1c += g_pc[bb][0] + g_pc[bb][1];
        }

        const float la_f = 0.5f * (S1f / (float)(BB * NF) + S2f / (float)(BB * MM));
        const float la_c = 0.5f * (S1c / (float)(BB * NC) + S2c / (float)(BB * MM));
        const float lref = Syd / (float)(BB * NF);

        float lrot = 0.0f, lgeo = 0.0f;
        for (int bb = 0; bb < BB; bb++) {
            const float dr = sqrtf(szf[bb]) - sqrtf(sznt[bb]);
            lrot += dr * dr;
            const float dg = (vfb[bb] - vnb[bb]) * (1.0f / 6.0f);
            lgeo += dg * dg;
        }
        lrot *= (1.0f / (float)BB);
        lgeo *= (1.0f / (float)BB);

        out[0] = lrot + lref + la_c + la_f + lgeo;
    }
}

extern "C" void kernel_launch(void* const* d_in, const int* in_sizes, int n_in,
                              void* d_out, int out_size)
{
    const float* sc = (const float*)d_in[0];  // source_coarse (B, 512, 3)
    const float* sf = (const float*)d_in[1];  // source_fine   (B, 8192, 3)
    const float* tp = (const float*)d_in[2];  // target_points (B, 8192, 3)
    float* out = (float*)d_out;

    dim3 g1(272, BB);
    nn_kernel<<<g1, NT>>>(sc, sf, tp);

    dim3 g2(66, BB);
    combine_kernel<<<g2, NT>>>(sc, sf, tp, out);
}

// round 12
// speedup vs baseline: 1.7601x; 1.1665x over previous
#include <cuda_runtime.h>
#include <math.h>

// Problem shapes (fixed by the dataset)
#define BB    2
#define NC    512
#define NF    8192
#define MM    8192
#define NT    256
#define SLICE 512       // targets per block slice
#define NSL   16        // slices (8192 / 512)
#define QPT   4         // queries per thread (main roles)
#define EPSF  1e-12f

typedef unsigned long long ull;

// ---------------- scratch (__device__ globals; no allocation allowed) ----------------
__device__ float g_av [BB][NSL][NF];     // fine->target partial min value per slice
__device__ int   g_ai [BB][NSL][NF];     // fine->target partial argmin index per slice
__device__ float g_tv [BB][NSL][MM];     // target->fine partial min per slice
__device__ float g_tcv[BB][NSL][MM];     // target->coarse partial min per coarse sub-slice
__device__ float g_cv [BB][NSL][NC];     // coarse->target partial min per slice
__device__ float g_nt [BB * NF * 3];     // gathered nearest target per fine point
__device__ float g_pf [BB][32][4];       // fine combine: sum d1, sum zf^2, sum znt^2, sum ydiff^2
__device__ float g_pt [BB][32][2];       // target combine: sum d2f, sum d2c
__device__ float g_pc [BB][2];           // coarse combine: sum d1c
__device__ float g_pv [BB][32][2];       // volume partials (interior triples): fine, new_target
__device__ unsigned int g_ticket;        // last-block ticket (wraps to 0 each launch)

// ---------------- packed f32x2 helpers (per-half bit-identical to scalar) ----------------
__device__ __forceinline__ ull pack2(float lo, float hi) {
    ull r; asm("mov.b64 %0, {%1, %2};" : "=l"(r) : "f"(lo), "f"(hi)); return r;
}
__device__ __forceinline__ void unpack2(ull v, float& lo, float& hi) {
    asm("mov.b64 {%0, %1}, %2;" : "=f"(lo), "=f"(hi) : "l"(v));
}
__device__ __forceinline__ ull mul2(ull a, ull b) {
    ull r; asm("mul.rn.f32x2 %0, %1, %2;" : "=l"(r) : "l"(a), "l"(b)); return r;
}
__device__ __forceinline__ ull fma2(ull a, ull b, ull c) {
    ull r; asm("fma.rn.f32x2 %0, %1, %2, %3;" : "=l"(r) : "l"(a), "l"(b), "l"(c)); return r;
}

// Warp sum (fixed shfl order -> deterministic); result valid on lane 0.
__device__ __forceinline__ float warpSum(float v) {
#pragma unroll
    for (int o = 16; o > 0; o >>= 1) v += __shfl_down_sync(0xFFFFFFFFu, v, o);
    return v;
}

// Fast deterministic block sum: warp shfl tree + 8-leader smem combine.
// Result valid on tid 0 only. 2 barriers per call.
__device__ __forceinline__ float blockSumFast(float v, float* sh) {
    const int lane = threadIdx.x & 31;
    const int w    = threadIdx.x >> 5;
    v = warpSum(v);
    if (lane == 0) sh[w] = v;
    __syncthreads();
    float r = 0.0f;
    if (threadIdx.x == 0) {
#pragma unroll
        for (int i = 0; i < NT / 32; i++) r += sh[i];
    }
    __syncthreads();   // protect sh reuse by next call
    return r;
}

// RAW pairs (argmin role — arithmetic must match the verified form exactly):
__device__ __forceinline__ void loadPairsRaw(ulonglong2* xy, ulonglong2* zw,
                                             const float* __restrict__ src,
                                             int t0, int count) {
    for (int p = threadIdx.x; p < count / 2; p += NT) {
        const int j0 = t0 + 2 * p;
        const float x0 = src[j0 * 3 + 0], y0 = src[j0 * 3 + 1], z0 = src[j0 * 3 + 2];
        const float x1 = src[j0 * 3 + 3], y1 = src[j0 * 3 + 4], z1 = src[j0 * 3 + 5];
        ulonglong2 a, b;
        a.x = pack2(x0, x1); a.y = pack2(y0, y1);
        b.x = pack2(z0, z1);
        b.y = pack2(x0 * x0 + y0 * y0 + z0 * z0,
                    x1 * x1 + y1 * y1 + z1 * z1);
        xy[p] = a; zw[p] = b;
    }
}

// SCALED pairs (min-only roles): store (-2x, -2y, -2z, |p|^2) -> 3 fma2 per pair.
__device__ __forceinline__ void loadPairsScaled(ulonglong2* xy, ulonglong2* zw,
                                                const float* __restrict__ src,
                                                int t0, int count) {
    for (int p = threadIdx.x; p < count / 2; p += NT) {
        const int j0 = t0 + 2 * p;
        const float x0 = src[j0 * 3 + 0], y0 = src[j0 * 3 + 1], z0 = src[j0 * 3 + 2];
        const float x1 = src[j0 * 3 + 3], y1 = src[j0 * 3 + 4], z1 = src[j0 * 3 + 5];
        ulonglong2 a, b;
        a.x = pack2(-2.0f * x0, -2.0f * x1);
        a.y = pack2(-2.0f * y0, -2.0f * y1);
        b.x = pack2(-2.0f * z0, -2.0f * z1);
        b.y = pack2(x0 * x0 + y0 * y0 + z0 * z0,
                    x1 * x1 + y1 * y1 + z1 * z1);
        xy[p] = a; zw[p] = b;
    }
}

// Main pass: grid = (272, BB).
__global__ void __launch_bounds__(NT) nn_kernel(const float* __restrict__ sc,
                                                const float* __restrict__ sf,
                                                const float* __restrict__ tp)
{
    __shared__ ulonglong2 tXY[SLICE / 2], tZW[SLICE / 2];
    __shared__ ulonglong2 cXY[16], cZW[16];   // coarse sub-slice (32 points)

    const int b   = blockIdx.y;
    const int bx  = blockIdx.x;
    const int tid = threadIdx.x;

    const float* tgt = tp + (size_t)b * MM * 3;
    const float* fin = sf + (size_t)b * NF * 3;
    const float* crs = sc + (size_t)b * NC * 3;

    if (bx < 128) {
        // ====== fine -> target : partial argmin over one slice (EXACT verified math) ======
        const int qb    = bx >> 4;
        const int slice = bx & 15;
        const int base  = slice * SLICE;

        loadPairsRaw(tXY, tZW, tgt, base, SLICE);

        ull qx2[QPT], qy2[QPT], qz2[QPT];
        float best[QPT];
        int   pb[QPT];
#pragma unroll
        for (int q = 0; q < QPT; q++) {
            const int qi = qb * (NT * QPT) + q * NT + tid;
            const float qx = fin[qi * 3 + 0];
            const float qy = fin[qi * 3 + 1];
            const float qz = fin[qi * 3 + 2];
            qx2[q] = pack2(qx, qx); qy2[q] = pack2(qy, qy); qz2[q] = pack2(qz, qz);
            best[q] = 3.0e38f; pb[q] = 0;
        }
        const ull NEG2 = pack2(-2.0f, -2.0f);
        __syncthreads();

#pragma unroll 4
        for (int p = 0; p < SLICE / 2; p++) {
            const ulonglong2 vxy = tXY[p];
            const ulonglong2 vzw = tZW[p];
#pragma unroll
            for (int q = 0; q < QPT; q++) {
                const ull xy2 = fma2(qz2[q], vzw.x, fma2(qy2[q], vxy.y, mul2(qx2[q], vxy.x)));
                const ull t2  = fma2(NEG2, xy2, vzw.y);
                float tlo, thi; unpack2(t2, tlo, thi);
                const float m = fminf(tlo, thi);
                if (m < best[q]) { best[q] = m; pb[q] = p; }
            }
        }
#pragma unroll
        for (int q = 0; q < QPT; q++) {
            const int qi = qb * (NT * QPT) + q * NT + tid;
            const int p = pb[q];
            const ulonglong2 vxy = tXY[p];
            const ulonglong2 vzw = tZW[p];
            const ull xy2 = fma2(qz2[q], vzw.x, fma2(qy2[q], vxy.y, mul2(qx2[q], vxy.x)));
            const ull t2  = fma2(NEG2, xy2, vzw.y);
            float tlo, thi; unpack2(t2, tlo, thi);
            const int jb = base + 2 * p + ((thi < tlo) ? 1 : 0);
            g_av[b][slice][qi] = best[q];
            g_ai[b][slice][qi] = jb;
        }
    } else if (bx < 256) {
        // ============ target -> fine (min) and target -> coarse (min), one slice ============
        const int r     = bx - 128;
        const int qb    = r >> 4;
        const int slice = r & 15;
        const int base  = slice * SLICE;

        loadPairsScaled(tXY, tZW, fin, base, SLICE);
        loadPairsScaled(cXY, cZW, crs, slice * 32, 32);

        ull qx2[QPT], qy2[QPT], qz2[QPT];
        float mf[QPT * 2], mc[QPT * 2];
#pragma unroll
        for (int q = 0; q < QPT; q++) {
            const int qj = qb * (NT * QPT) + q * NT + tid;
            const float qx = tgt[qj * 3 + 0];
            const float qy = tgt[qj * 3 + 1];
            const float qz = tgt[qj * 3 + 2];
            qx2[q] = pack2(qx, qx); qy2[q] = pack2(qy, qy); qz2[q] = pack2(qz, qz);
            mf[2 * q] = 3.0e38f; mf[2 * q + 1] = 3.0e38f;
            mc[2 * q] = 3.0e38f; mc[2 * q + 1] = 3.0e38f;
        }
        __syncthreads();

#pragma unroll 4
        for (int p = 0; p < SLICE / 2; p++) {
            const ulonglong2 vxy = tXY[p];
            const ulonglong2 vzw = tZW[p];
#pragma unroll
            for (int q = 0; q < QPT; q++) {
                const ull t2 = fma2(qx2[q], vxy.x, fma2(qy2[q], vxy.y, fma2(qz2[q], vzw.x, vzw.y)));
                float tlo, thi; unpack2(t2, tlo, thi);
                mf[2 * q]     = fminf(mf[2 * q],     tlo);
                mf[2 * q + 1] = fminf(mf[2 * q + 1], thi);
            }
        }
#pragma unroll
        for (int p = 0; p < 16; p++) {
            const ulonglong2 vxy = cXY[p];
            const ulonglong2 vzw = cZW[p];
#pragma unroll
            for (int q = 0; q < QPT; q++) {
                const ull t2 = fma2(qx2[q], vxy.x, fma2(qy2[q], vxy.y, fma2(qz2[q], vzw.x, vzw.y)));
                float tlo, thi; unpack2(t2, tlo, thi);
                mc[2 * q]     = fminf(mc[2 * q],     tlo);
                mc[2 * q + 1] = fminf(mc[2 * q + 1], thi);
            }
        }
#pragma unroll
        for (int q = 0; q < QPT; q++) {
            const int qj = qb * (NT * QPT) + q * NT + tid;
            g_tv [b][slice][qj] = fminf(mf[2 * q], mf[2 * q + 1]);
            g_tcv[b][slice][qj] = fminf(mc[2 * q], mc[2 * q + 1]);
        }
    } else {
        // ================= coarse -> target : partial min over one slice =================
        const int slice = bx - 256;
        const int base  = slice * SLICE;

        loadPairsScaled(tXY, tZW, tgt, base, SLICE);

        ull qx2[2], qy2[2], qz2[2];
        float m[4];
#pragma unroll
        for (int q = 0; q < 2; q++) {
            const int ci = q * NT + tid;
            const float qx = crs[ci * 3 + 0];
            const float qy = crs[ci * 3 + 1];
            const float qz = crs[ci * 3 + 2];
            qx2[q] = pack2(qx, qx); qy2[q] = pack2(qy, qy); qz2[q] = pack2(qz, qz);
            m[2 * q] = 3.0e38f; m[2 * q + 1] = 3.0e38f;
        }
        __syncthreads();

#pragma unroll 4
        for (int p = 0; p < SLICE / 2; p++) {
            const ulonglong2 vxy = tXY[p];
            const ulonglong2 vzw = tZW[p];
#pragma unroll
            for (int q = 0; q < 2; q++) {
                const ull t2 = fma2(qx2[q], vxy.x, fma2(qy2[q], vxy.y, fma2(qz2[q], vzw.x, vzw.y)));
                float tlo, thi; unpack2(t2, tlo, thi);
                m[2 * q]     = fminf(m[2 * q],     tlo);
                m[2 * q + 1] = fminf(m[2 * q + 1], thi);
            }
        }
#pragma unroll
        for (int q = 0; q < 2; q++) {
            const int ci = q * NT + tid;
            g_cv[b][slice][ci] = fminf(m[2 * q], m[2 * q + 1]);
        }
    }
}

// Combine + fused tail. grid = (66, BB). Last block (ticket) finalizes.
__global__ void __launch_bounds__(NT) combine_kernel(const float* __restrict__ sc,
                                                     const float* __restrict__ sf,
                                                     const float* __restrict__ tp,
                                                     float* __restrict__ out)
{
    __shared__ float sred[NT / 32];
    __shared__ float sfin[NT][3], snt[NT][3];
    __shared__ bool  s_last;
    const int b   = blockIdx.y;
    const int bx  = blockIdx.x;
    const int tid = threadIdx.x;

    if (bx < 32) {
        const int qi = bx * NT + tid;
        // tournament on (value, slice): ascending strict < keeps earliest slice;
        // only the winning slice's index is loaded afterwards (same result as before).
        float best = g_av[b][0][qi]; int sb = 0;
#pragma unroll
        for (int s = 1; s < NSL; s++) {
            const float v = g_av[b][s][qi];
            if (v < best) { best = v; sb = s; }
        }
        const int jb = g_ai[b][sb][qi];

        const float* fin = sf + (size_t)b * NF * 3;
        const float* tgt = tp + (size_t)b * MM * 3;
        const float qx = fin[qi * 3 + 0];
        const float qy = fin[qi * 3 + 1];
        const float qz = fin[qi * 3 + 2];
        const float qq = qx * qx + qy * qy + qz * qz;

        const float d  = fmaxf(qq + best, 0.0f);
        const float d1 = sqrtf(fmaxf(d, EPSF));

        const float nx = tgt[jb * 3 + 0];
        const float ny = tgt[jb * 3 + 1];
        const float nz = tgt[jb * 3 + 2];
        const int o = (b * NF + qi) * 3;
        g_nt[o + 0] = nx; g_nt[o + 1] = ny; g_nt[o + 2] = nz;

        sfin[tid][0] = qx; sfin[tid][1] = qy; sfin[tid][2] = qz;
        snt [tid][0] = nx; snt [tid][1] = ny; snt [tid][2] = nz;
        __syncthreads();   // snt/sfin visible for volume triples

        // interior wedge-volume triples (local rows tid, tid+1, tid+2)
        float vf = 0.0f, vn = 0.0f;
        if (tid < NT - 2) {
            float a0 = sfin[tid][0],   a1 = sfin[tid][1],   a2 = sfin[tid][2];
            float e0 = sfin[tid+1][0], e1 = sfin[tid+1][1], e2 = sfin[tid+1][2];
            float c0 = sfin[tid+2][0], c1 = sfin[tid+2][1], c2 = sfin[tid+2][2];
            float cx = a1 * e2 - a2 * e1;
            float cy = a2 * e0 - a0 * e2;
            float cz = a0 * e1 - a1 * e0;
            vf = cx * c0 + cy * c1 + cz * c2;

            a0 = snt[tid][0];   a1 = snt[tid][1];   a2 = snt[tid][2];
            e0 = snt[tid+1][0]; e1 = snt[tid+1][1]; e2 = snt[tid+1][2];
            c0 = snt[tid+2][0]; c1 = snt[tid+2][1]; c2 = snt[tid+2][2];
            cx = a1 * e2 - a2 * e1;
            cy = a2 * e0 - a0 * e2;
            cz = a0 * e1 - a1 * e0;
            vn = cx * c0 + cy * c1 + cz * c2;
        }

        const float yd = qy - ny;
        const float r0 = blockSumFast(d1,      sred);
        const float r1 = blockSumFast(qz * qz, sred);
        const float r2 = blockSumFast(nz * nz, sred);
        const float r3 = blockSumFast(yd * yd, sred);
        const float r4 = blockSumFast(vf, sred);
        const float r5 = blockSumFast(vn, sred);
        if (tid == 0) {
            g_pf[b][bx][0] = r0; g_pf[b][bx][1] = r1;
            g_pf[b][bx][2] = r2; g_pf[b][bx][3] = r3;
            g_pv[b][bx][0] = r4; g_pv[b][bx][1] = r5;
        }
    } else if (bx < 64) {
        const int qj = (bx - 32) * NT + tid;
        float mF = g_tv[b][0][qj], mC = g_tcv[b][0][qj];
#pragma unroll
        for (int s = 1; s < NSL; s++) {
            mF = fminf(mF, g_tv[b][s][qj]);
            mC = fminf(mC, g_tcv[b][s][qj]);
        }
        const float* tgt = tp + (size_t)b * MM * 3;
        const float qx = tgt[qj * 3 + 0];
        const float qy = tgt[qj * 3 + 1];
        const float qz = tgt[qj * 3 + 2];
        const float qq = qx * qx + qy * qy + qz * qz;

        const float d2f = sqrtf(fmaxf(fmaxf(qq + mF, 0.0f), EPSF));
        const float d2c = sqrtf(fmaxf(fmaxf(qq + mC, 0.0f), EPSF));
        const float r0 = blockSumFast(d2f, sred);
        const float r1 = blockSumFast(d2c, sred);
        if (tid == 0) { g_pt[b][bx - 32][0] = r0; g_pt[b][bx - 32][1] = r1; }
    } else {
        const int ci = (bx - 64) * NT + tid;
        float m = g_cv[b][0][ci];
#pragma unroll
        for (int s = 1; s < NSL; s++) m = fminf(m, g_cv[b][s][ci]);

        const float* crs = sc + (size_t)b * NC * 3;
        const float qx = crs[ci * 3 + 0];
        const float qy = crs[ci * 3 + 1];
        const float qz = crs[ci * 3 + 2];
        const float qq = qx * qx + qy * qy + qz * qz;

        const float d1c = sqrtf(fmaxf(fmaxf(qq + m, 0.0f), EPSF));
        const float r0 = blockSumFast(d1c, sred);
        if (tid == 0) g_pc[b][bx - 64] = r0;
    }

    // ---------------- last-block fused tail ----------------
    __threadfence();
    if (tid == 0) {
        const unsigned int total = 66 * BB;
        const unsigned int old = atomicInc(&g_ticket, total - 1);
        s_last = (old == total - 1);
    }
    __syncthreads();
    if (!s_last) return;

    // Boundary volume triples (block-parallel): i = 256*k + 254/255, k=0..30
    __shared__ float svol[BB][2];
    for (int bb = 0; bb < BB; bb++) {
        float vf = 0.0f, vn = 0.0f;
        for (int t = tid; t < 62; t += NT) {
            const int k = t >> 1;
            const int i = 256 * k + 254 + (t & 1);
            const float* p = sf + (size_t)bb * NF * 3 + (size_t)i * 3;
            float a0 = p[0], a1 = p[1], a2 = p[2];
            float e0 = p[3], e1 = p[4], e2 = p[5];
            float c0 = p[6], c1 = p[7], c2 = p[8];
            float cx = a1 * e2 - a2 * e1;
            float cy = a2 * e0 - a0 * e2;
            float cz = a0 * e1 - a1 * e0;
            vf += cx * c0 + cy * c1 + cz * c2;

            const float* q = g_nt + ((size_t)bb * NF + i) * 3;
            a0 = q[0]; a1 = q[1]; a2 = q[2];
            e0 = q[3]; e1 = q[4]; e2 = q[5];
            c0 = q[6]; c1 = q[7]; c2 = q[8];
            cx = a1 * e2 - a2 * e1;
            cy = a2 * e0 - a0 * e2;
            cz = a0 * e1 - a1 * e0;
            vn += cx * c0 + cy * c1 + cz * c2;
        }
        const float r0 = blockSumFast(vf, sred);
        const float r1 = blockSumFast(vn, sred);
        if (tid == 0) { svol[bb][0] = r0; svol[bb][1] = r1; }
    }
    __syncthreads();

    // Parallel finalize: warp 0, lane k owns partial slot k (32 slots per array).
    if (tid < 32) {
        float S1f = 0.0f, Syd = 0.0f, S2f = 0.0f, S2c = 0.0f;
        float szf[BB], sznt[BB], vfb[BB], vnb[BB];
#pragma unroll
        for (int bb = 0; bb < BB; bb++) {
            const float a0 = warpSum(g_pf[bb][tid][0]);
            const float a1 = warpSum(g_pf[bb][tid][1]);
            const float a2 = warpSum(g_pf[bb][tid][2]);
            const float a3 = warpSum(g_pf[bb][tid][3]);
            const float b0 = warpSum(g_pt[bb][tid][0]);
            const float b1 = warpSum(g_pt[bb][tid][1]);
            const float v0 = warpSum(g_pv[bb][tid][0]);
            const float v1 = warpSum(g_pv[bb][tid][1]);
            if (tid == 0) {
                S1f += a0; szf[bb] = a1; sznt[bb] = a2; Syd += a3;
                S2f += b0; S2c += b1;
                vfb[bb] = v0 + svol[bb][0];
                vnb[bb] = v1 + svol[bb][1];
            }
        }
        if (tid == 0) {
            float S1c = 0.0f;
#pragma unroll
            for (int bb = 0; bb < BB; bb++) S1c += g_pc[bb][0] + g_pc[bb][1];

            const float la_f = 0.5f * (S1f / (float)(BB * NF) + S2f / (float)(BB * MM));
            const float la_c = 0.5f * (S1c / (float)(BB * NC) + S2c / (float)(BB * MM));
            const float lref = Syd / (float)(BB * NF);

            float lrot = 0.0f, lgeo = 0.0f;
#pragma unroll
            for (int bb = 0; bb < BB; bb++) {
                const float dr = sqrtf(szf[bb]) - sqrtf(sznt[bb]);
                lrot += dr * dr;
                const float dg = (vfb[bb] - vnb[bb]) * (1.0f / 6.0f);
                lgeo += dg * dg;
            }
            lrot *= (1.0f / (float)BB);
            lgeo *= (1.0f / (float)BB);

            out[0] = lrot + lref + la_c + la_f + lgeo;
        }
    }
}

extern "C" void kernel_launch(void* const* d_in, const int* in_sizes, int n_in,
                              void* d_out, int out_size)
{
    const float* sc = (const float*)d_in[0];  // source_coarse (B, 512, 3)
    const float* sf = (const float*)d_in[1];  // source_fine   (B, 8192, 3)
    const float* tp = (const float*)d_in[2];  // target_points (B, 8192, 3)
    float* out = (float*)d_out;

    dim3 g1(272, BB);
    nn_kernel<<<g1, NT>>>(sc, sf, tp);

    dim3 g2(66, BB);
    combine_kernel<<<g2, NT>>>(sc, sf, tp, out);
}